// round 1
// baseline (speedup 1.0000x reference)
#include <cuda_runtime.h>
#include <cuda_fp16.h>
#include <stdint.h>

#define N_NODES    100000
#define N_EDGES    300000
#define NUM_GRAPHS 128
#define HIDDEN     256
#define SEM_IN     1536
#define MAX_CHILD  200

// Scratch (device globals are the sanctioned scratch mechanism)
__device__ float g_h[(size_t)N_NODES * HIDDEN];     // current node features
__device__ float g_z[(size_t)N_NODES * HIDDEN];     // h + aggregated messages
__device__ float g_t[(size_t)N_NODES * HIDDEN];     // MLP hidden
__device__ float g_pool[NUM_GRAPHS * HIDDEN];

// ---------------------------------------------------------------------------
// Tensor-core GEMM:  C[M,256] = A[M,K] (fp32, cast fp16) @ B[K,256] (fp32, cast fp16)
// BM=128, BN=128, BK=32, 256 threads (8 warps as 2x4), warp tile 64x32,
// mma.m16n8k16 f16 -> f32 accum. 2-stage smem pipeline, reg-staged loads
// (fp32 LDG -> cvt -> fp16 STS).
// ---------------------------------------------------------------------------
#define BM 128
#define BN 128
#define BK 32
#define SA_STRIDE 40    // 32 + 8 pad (halves): 80B row stride, conflict-free LDSM
#define SB_STRIDE 136   // 128 + 8 pad

#define MODE_EMBED    0  // C += sem_b + label_emb[x0] + type_emb[x1]; write out1 & out2
#define MODE_HIDDEN   1  // C = relu(C + bias); write out1
#define MODE_OUT_DUAL 2  // C = C + bias; write out1 & out2
#define MODE_OUT      3  // C = C + bias; write out1

template<int MODE>
__global__ void __launch_bounds__(256) gemm_kernel(
    const float* __restrict__ A, const float* __restrict__ B,
    const float* __restrict__ bias,
    const int*   __restrict__ xidx,
    const float* __restrict__ label_emb,
    const float* __restrict__ type_emb,
    float* __restrict__ out1, float* __restrict__ out2,
    int M, int K)
{
    __shared__ __align__(16) __half sA[2][BM * SA_STRIDE];
    __shared__ __align__(16) __half sB[2][BK * SB_STRIDE];

    const int tid  = threadIdx.x;
    const int lane = tid & 31;
    const int warp = tid >> 5;
    const int wm   = warp >> 2;     // 0..1  -> 64-row span
    const int wn   = warp & 3;      // 0..3  -> 32-col span
    const int mBase = blockIdx.x * BM;
    const int nBase = blockIdx.y * BN;

    const int a_row = tid >> 3;          // 0..31 (then +32*i)
    const int a_col = (tid & 7) << 2;    // 0,4,...,28
    const int b_row = tid >> 5;          // 0..7 (then +8*i)
    const int b_col = (tid & 31) << 2;   // 0,4,...,124

    const int KT = K / BK;

    float4 ra[4], rb[4];
    float acc[4][4][4];
    #pragma unroll
    for (int i = 0; i < 4; i++)
        #pragma unroll
        for (int j = 0; j < 4; j++)
            #pragma unroll
            for (int q = 0; q < 4; q++) acc[i][j][q] = 0.f;

    auto ldg = [&](int kt) {
        #pragma unroll
        for (int i = 0; i < 4; i++) {
            int r = mBase + a_row + i * 32;
            if (r < M) ra[i] = *(const float4*)(A + (size_t)r * K + kt * BK + a_col);
            else       ra[i] = make_float4(0.f, 0.f, 0.f, 0.f);
        }
        #pragma unroll
        for (int i = 0; i < 4; i++) {
            int r = kt * BK + b_row + i * 8;
            rb[i] = *(const float4*)(B + (size_t)r * HIDDEN + nBase + b_col);
        }
    };
    auto sts = [&](int st) {
        #pragma unroll
        for (int i = 0; i < 4; i++) {
            __half2* p = (__half2*)&sA[st][(a_row + i * 32) * SA_STRIDE + a_col];
            p[0] = __floats2half2_rn(ra[i].x, ra[i].y);
            p[1] = __floats2half2_rn(ra[i].z, ra[i].w);
            __half2* q = (__half2*)&sB[st][(b_row + i * 8) * SB_STRIDE + b_col];
            q[0] = __floats2half2_rn(rb[i].x, rb[i].y);
            q[1] = __floats2half2_rn(rb[i].z, rb[i].w);
        }
    };

    ldg(0);
    sts(0);
    __syncthreads();

    for (int kt = 0; kt < KT; kt++) {
        const int st = kt & 1;
        if (kt + 1 < KT) ldg(kt + 1);

        #pragma unroll
        for (int ks = 0; ks < 2; ks++) {
            uint32_t af[4][4], bf[2][4];
            #pragma unroll
            for (int mi = 0; mi < 4; mi++) {
                const __half* p = &sA[st][(wm * 64 + mi * 16 + (lane & 15)) * SA_STRIDE
                                          + ks * 16 + (lane >> 4) * 8];
                uint32_t addr = (uint32_t)__cvta_generic_to_shared(p);
                asm volatile("ldmatrix.sync.aligned.m8n8.x4.shared.b16 {%0,%1,%2,%3}, [%4];"
                             : "=r"(af[mi][0]), "=r"(af[mi][1]), "=r"(af[mi][2]), "=r"(af[mi][3])
                             : "r"(addr));
            }
            #pragma unroll
            for (int p2 = 0; p2 < 2; p2++) {
                int krow = ks * 16 + (lane & 7) + ((lane >> 3) & 1) * 8;
                int ncol = wn * 32 + p2 * 16 + (lane >> 4) * 8;
                const __half* p = &sB[st][krow * SB_STRIDE + ncol];
                uint32_t addr = (uint32_t)__cvta_generic_to_shared(p);
                asm volatile("ldmatrix.sync.aligned.m8n8.x4.trans.shared.b16 {%0,%1,%2,%3}, [%4];"
                             : "=r"(bf[p2][0]), "=r"(bf[p2][1]), "=r"(bf[p2][2]), "=r"(bf[p2][3])
                             : "r"(addr));
            }
            #pragma unroll
            for (int mi = 0; mi < 4; mi++) {
                #pragma unroll
                for (int ni = 0; ni < 4; ni++) {
                    uint32_t b0 = bf[ni >> 1][(ni & 1) * 2 + 0];
                    uint32_t b1 = bf[ni >> 1][(ni & 1) * 2 + 1];
                    asm volatile(
                        "mma.sync.aligned.m16n8k16.row.col.f32.f16.f16.f32 "
                        "{%0,%1,%2,%3}, {%4,%5,%6,%7}, {%8,%9}, {%0,%1,%2,%3};"
                        : "+f"(acc[mi][ni][0]), "+f"(acc[mi][ni][1]),
                          "+f"(acc[mi][ni][2]), "+f"(acc[mi][ni][3])
                        : "r"(af[mi][0]), "r"(af[mi][1]), "r"(af[mi][2]), "r"(af[mi][3]),
                          "r"(b0), "r"(b1));
                }
            }
        }
        if (kt + 1 < KT) sts(st ^ 1);
        __syncthreads();
    }

    // Epilogue. mma accum mapping: c0,c1 -> row lane/4, cols (lane%4)*2(+1);
    //                              c2,c3 -> row lane/4 + 8.
    #pragma unroll
    for (int mi = 0; mi < 4; mi++) {
        int r0 = mBase + wm * 64 + mi * 16 + (lane >> 2);
        #pragma unroll
        for (int hh = 0; hh < 2; hh++) {
            int r = r0 + hh * 8;
            if (r >= M) continue;
            int x0 = 0, x1 = 0;
            if (MODE == MODE_EMBED) { x0 = xidx[2 * r]; x1 = xidx[2 * r + 1]; }
            #pragma unroll
            for (int ni = 0; ni < 4; ni++) {
                int c = nBase + wn * 32 + ni * 8 + (lane & 3) * 2;
                float v0 = acc[mi][ni][hh * 2 + 0];
                float v1 = acc[mi][ni][hh * 2 + 1];
                v0 += bias[c];
                v1 += bias[c + 1];
                if (MODE == MODE_EMBED) {
                    v0 += label_emb[(size_t)x0 * HIDDEN + c]     + type_emb[x1 * HIDDEN + c];
                    v1 += label_emb[(size_t)x0 * HIDDEN + c + 1] + type_emb[x1 * HIDDEN + c + 1];
                }
                if (MODE == MODE_HIDDEN) { v0 = fmaxf(v0, 0.f); v1 = fmaxf(v1, 0.f); }
                float2 vv = make_float2(v0, v1);
                *(float2*)(out1 + (size_t)r * HIDDEN + c) = vv;
                if (MODE == MODE_EMBED || MODE == MODE_OUT_DUAL)
                    *(float2*)(out2 + (size_t)r * HIDDEN + c) = vv;
            }
        }
    }
}

// ---------------------------------------------------------------------------
// Edge kernel: one warp per edge.
//   msg = relu(h[src] + role_emb[ea0] + child_emb[clip(ea1)]);  z[dst] += msg
// role/child tables are tiny (L2-resident); scatter via red.global.add.v4.f32.
// ---------------------------------------------------------------------------
__global__ void __launch_bounds__(256) edge_kernel(
    const int*   __restrict__ eattr,
    const int*   __restrict__ eidx,
    const float* __restrict__ role,
    const float* __restrict__ child,
    const float* __restrict__ h,
    float*       __restrict__ z)
{
    int w = blockIdx.x * 8 + (threadIdx.x >> 5);
    if (w >= N_EDGES) return;
    int lane = threadIdx.x & 31;

    int rrole = __ldg(&eattr[2 * w]);
    int cix   = __ldg(&eattr[2 * w + 1]);
    cix = min(max(cix, 0), MAX_CHILD - 1);
    int src = __ldg(&eidx[w]);
    int dst = __ldg(&eidx[N_EDGES + w]);

    const float4* hs = (const float4*)(h + (size_t)src * HIDDEN);
    const float4* rp = (const float4*)(role + rrole * HIDDEN);
    const float4* cp = (const float4*)(child + cix * HIDDEN);
    float* zd = z + (size_t)dst * HIDDEN;

    #pragma unroll
    for (int i = 0; i < 2; i++) {
        int c4 = lane + i * 32;   // 64 float4 per row
        float4 a = hs[c4], b = rp[c4], c = cp[c4];
        float m0 = fmaxf(a.x + b.x + c.x, 0.f);
        float m1 = fmaxf(a.y + b.y + c.y, 0.f);
        float m2 = fmaxf(a.z + b.z + c.z, 0.f);
        float m3 = fmaxf(a.w + b.w + c.w, 0.f);
        asm volatile("red.global.add.v4.f32 [%0], {%1,%2,%3,%4};"
                     :: "l"(zd + c4 * 4), "f"(m0), "f"(m1), "f"(m2), "f"(m3)
                     : "memory");
    }
}

// ---------------------------------------------------------------------------
// Pool: batch is sorted -> binary-search per-graph range, one CTA per graph,
// thread t accumulates column t (coalesced row reads).
// ---------------------------------------------------------------------------
__global__ void __launch_bounds__(HIDDEN) pool_kernel(
    const float* __restrict__ h,
    const int*   __restrict__ batch,
    float*       __restrict__ pooled)
{
    int g = blockIdx.x;
    int t = threadIdx.x;

    int lo = 0, hi = N_NODES;
    while (lo < hi) { int mid = (lo + hi) >> 1; if (batch[mid] < g) lo = mid + 1; else hi = mid; }
    int start = lo;
    hi = N_NODES;
    while (lo < hi) { int mid = (lo + hi) >> 1; if (batch[mid] < g + 1) lo = mid + 1; else hi = mid; }
    int end = lo;

    float acc = 0.f;
    for (int r = start; r < end; r++) acc += h[(size_t)r * HIDDEN + t];
    float cnt = (float)(end - start);
    pooled[g * HIDDEN + t] = acc / fmaxf(cnt, 1.f);
}

// ---------------------------------------------------------------------------
// Projection: out[g, t] = pooled[g, :] @ proj_W[:, t] + proj_b[t]   (tiny)
// ---------------------------------------------------------------------------
__global__ void __launch_bounds__(HIDDEN) proj_kernel(
    const float* __restrict__ pooled,
    const float* __restrict__ W,
    const float* __restrict__ b,
    float*       __restrict__ out)
{
    int g = blockIdx.x;
    int t = threadIdx.x;
    float acc = b[t];
    #pragma unroll 8
    for (int k = 0; k < HIDDEN; k++)
        acc += pooled[g * HIDDEN + k] * W[k * HIDDEN + t];
    out[g * HIDDEN + t] = acc;
}

// ---------------------------------------------------------------------------
extern "C" void kernel_launch(void* const* d_in, const int* in_sizes, int n_in,
                              void* d_out, int out_size)
{
    const int*   x        = (const int*)  d_in[0];
    const float* x_sem    = (const float*)d_in[1];
    const int*   eattr    = (const int*)  d_in[2];
    const int*   eidx     = (const int*)  d_in[3];
    const int*   batch    = (const int*)  d_in[4];
    const float* label    = (const float*)d_in[5];
    const float* type_emb = (const float*)d_in[6];
    const float* sem_W    = (const float*)d_in[7];
    const float* sem_b    = (const float*)d_in[8];
    const float* role     = (const float*)d_in[9];
    const float* child    = (const float*)d_in[10];
    const float* W1_0     = (const float*)d_in[11];
    const float* b1_0     = (const float*)d_in[12];
    const float* W2_0     = (const float*)d_in[13];
    const float* b2_0     = (const float*)d_in[14];
    const float* W1_1     = (const float*)d_in[15];
    const float* b1_1     = (const float*)d_in[16];
    const float* W2_1     = (const float*)d_in[17];
    const float* b2_1     = (const float*)d_in[18];
    const float* proj_W   = (const float*)d_in[19];
    const float* proj_b   = (const float*)d_in[20];
    float* out = (float*)d_out;

    float *hP, *zP, *tP, *pP;
    cudaGetSymbolAddress((void**)&hP, g_h);
    cudaGetSymbolAddress((void**)&zP, g_z);
    cudaGetSymbolAddress((void**)&tP, g_t);
    cudaGetSymbolAddress((void**)&pP, g_pool);

    dim3 gemm_grid((N_NODES + BM - 1) / BM, HIDDEN / BN);
    int edge_blocks = (N_EDGES + 7) / 8;

    // h = label_emb[x0] + type_emb[x1] + x_sem @ sem_W + sem_b ; z = h
    gemm_kernel<MODE_EMBED><<<gemm_grid, 256>>>(
        x_sem, sem_W, sem_b, x, label, type_emb, hP, zP, N_NODES, SEM_IN);

    // --- GINE layer 0 ---
    edge_kernel<<<edge_blocks, 256>>>(eattr, eidx, role, child, hP, zP);
    gemm_kernel<MODE_HIDDEN><<<gemm_grid, 256>>>(
        zP, W1_0, b1_0, nullptr, nullptr, nullptr, tP, nullptr, N_NODES, HIDDEN);
    gemm_kernel<MODE_OUT_DUAL><<<gemm_grid, 256>>>(
        tP, W2_0, b2_0, nullptr, nullptr, nullptr, hP, zP, N_NODES, HIDDEN);

    // --- GINE layer 1 ---
    edge_kernel<<<edge_blocks, 256>>>(eattr, eidx, role, child, hP, zP);
    gemm_kernel<MODE_HIDDEN><<<gemm_grid, 256>>>(
        zP, W1_1, b1_1, nullptr, nullptr, nullptr, tP, nullptr, N_NODES, HIDDEN);
    gemm_kernel<MODE_OUT><<<gemm_grid, 256>>>(
        tP, W2_1, b2_1, nullptr, nullptr, nullptr, hP, nullptr, N_NODES, HIDDEN);

    // --- pool + projection ---
    pool_kernel<<<NUM_GRAPHS, HIDDEN>>>(hP, batch, pP);
    proj_kernel<<<NUM_GRAPHS, HIDDEN>>>(pP, proj_W, proj_b, out);
}

// round 2
// speedup vs baseline: 1.0992x; 1.0992x over previous
#include <cuda_runtime.h>
#include <cuda_fp16.h>
#include <stdint.h>

#define N_NODES    100000
#define N_EDGES    300000
#define NUM_GRAPHS 128
#define HIDDEN     256
#define SEM_IN     1536
#define MAX_CHILD  200

// Scratch
__device__ __half g_h[(size_t)N_NODES * HIDDEN];   // node features (fp16)
__device__ float  g_z[(size_t)N_NODES * HIDDEN];   // h + agg (fp32, atomic target)
__device__ float  g_pool[NUM_GRAPHS * HIDDEN];

#define BM 128
#define BN 256
#define BK 32
#define SA_STRIDE 40    // halves: 32+8 pad -> conflict-free ldmatrix
#define SB_STRIDE 264   // halves: 256+8 pad
#define ST_STRIDE 264   // t staging stride (halves)

#define SA_ELEMS (2 * BM * SA_STRIDE)        // per-kernel double-buffered A
#define SB_ELEMS (2 * BK * SB_STRIDE)
#define ST_ELEMS (BM * ST_STRIDE)

// ---------------------------------------------------------------------------
// mma helpers
// ---------------------------------------------------------------------------
__device__ __forceinline__ void ldsm_x4(uint32_t* r, const __half* p) {
    uint32_t a = (uint32_t)__cvta_generic_to_shared(p);
    asm volatile("ldmatrix.sync.aligned.m8n8.x4.shared.b16 {%0,%1,%2,%3}, [%4];"
                 : "=r"(r[0]), "=r"(r[1]), "=r"(r[2]), "=r"(r[3]) : "r"(a));
}
__device__ __forceinline__ void ldsm_x4t(uint32_t* r, const __half* p) {
    uint32_t a = (uint32_t)__cvta_generic_to_shared(p);
    asm volatile("ldmatrix.sync.aligned.m8n8.x4.trans.shared.b16 {%0,%1,%2,%3}, [%4];"
                 : "=r"(r[0]), "=r"(r[1]), "=r"(r[2]), "=r"(r[3]) : "r"(a));
}
__device__ __forceinline__ void mma16816(float* c, const uint32_t* a,
                                         uint32_t b0, uint32_t b1) {
    asm volatile(
        "mma.sync.aligned.m16n8k16.row.col.f32.f16.f16.f32 "
        "{%0,%1,%2,%3}, {%4,%5,%6,%7}, {%8,%9}, {%0,%1,%2,%3};"
        : "+f"(c[0]), "+f"(c[1]), "+f"(c[2]), "+f"(c[3])
        : "r"(a[0]), "r"(a[1]), "r"(a[2]), "r"(a[3]), "r"(b0), "r"(b1));
}

// ---------------------------------------------------------------------------
// Embed GEMM: h16/z32 = x_sem @ sem_W + sem_b + label_emb[x0] + type_emb[x1]
// BM=128, BN=256 (full HIDDEN: A read exactly once), BK=32, 512 threads.
// ---------------------------------------------------------------------------
__global__ void __launch_bounds__(512) embed_gemm(
    const float* __restrict__ A, const float* __restrict__ B,
    const float* __restrict__ bias,
    const int*   __restrict__ xidx,
    const float* __restrict__ label_emb,
    const float* __restrict__ type_emb,
    __half* __restrict__ h_out, float* __restrict__ z_out,
    int M, int K)
{
    extern __shared__ __half smem[];
    __half* sA = smem;               // [2][BM*SA_STRIDE]
    __half* sB = smem + SA_ELEMS;    // [2][BK*SB_STRIDE]

    const int tid  = threadIdx.x;
    const int lane = tid & 31;
    const int warp = tid >> 5;
    const int wm   = warp >> 3;       // 0..1
    const int wn   = warp & 7;        // 0..7
    const int mBase = blockIdx.x * BM;

    const int a_row = tid >> 3;          // 0..63 (+64)
    const int a_col = (tid & 7) << 2;
    const int b_row = tid >> 6;          // 0..7 (+8*i)
    const int b_col = (tid & 63) << 2;

    const int KT = K / BK;

    float4 ra[2], rb[4];
    float acc[4][4][4];
    #pragma unroll
    for (int i = 0; i < 4; i++)
        #pragma unroll
        for (int j = 0; j < 4; j++)
            #pragma unroll
            for (int q = 0; q < 4; q++) acc[i][j][q] = 0.f;

    auto ldg = [&](int kt) {
        #pragma unroll
        for (int i = 0; i < 2; i++) {
            int r = mBase + a_row + i * 64;
            if (r < M) ra[i] = *(const float4*)(A + (size_t)r * K + kt * BK + a_col);
            else       ra[i] = make_float4(0.f, 0.f, 0.f, 0.f);
        }
        #pragma unroll
        for (int i = 0; i < 4; i++) {
            int r = kt * BK + b_row + i * 8;
            rb[i] = *(const float4*)(B + (size_t)r * HIDDEN + b_col);
        }
    };
    auto sts = [&](int st) {
        #pragma unroll
        for (int i = 0; i < 2; i++) {
            __half2* p = (__half2*)&sA[st * BM * SA_STRIDE + (a_row + i * 64) * SA_STRIDE + a_col];
            p[0] = __floats2half2_rn(ra[i].x, ra[i].y);
            p[1] = __floats2half2_rn(ra[i].z, ra[i].w);
        }
        #pragma unroll
        for (int i = 0; i < 4; i++) {
            __half2* q = (__half2*)&sB[st * BK * SB_STRIDE + (b_row + i * 8) * SB_STRIDE + b_col];
            q[0] = __floats2half2_rn(rb[i].x, rb[i].y);
            q[1] = __floats2half2_rn(rb[i].z, rb[i].w);
        }
    };

    ldg(0); sts(0); __syncthreads();

    for (int kt = 0; kt < KT; kt++) {
        const int st = kt & 1;
        if (kt + 1 < KT) ldg(kt + 1);
        #pragma unroll
        for (int ks = 0; ks < 2; ks++) {
            uint32_t af[4][4], bf[2][4];
            #pragma unroll
            for (int mi = 0; mi < 4; mi++)
                ldsm_x4(af[mi], &sA[st * BM * SA_STRIDE
                         + (wm * 64 + mi * 16 + (lane & 15)) * SA_STRIDE
                         + ks * 16 + (lane >> 4) * 8]);
            #pragma unroll
            for (int p2 = 0; p2 < 2; p2++) {
                int krow = ks * 16 + (lane & 7) + ((lane >> 3) & 1) * 8;
                int ncol = wn * 32 + p2 * 16 + (lane >> 4) * 8;
                ldsm_x4t(bf[p2], &sB[st * BK * SB_STRIDE + krow * SB_STRIDE + ncol]);
            }
            #pragma unroll
            for (int mi = 0; mi < 4; mi++)
                #pragma unroll
                for (int ni = 0; ni < 4; ni++)
                    mma16816(acc[mi][ni], af[mi],
                             bf[ni >> 1][(ni & 1) * 2 + 0], bf[ni >> 1][(ni & 1) * 2 + 1]);
        }
        if (kt + 1 < KT) sts(st ^ 1);
        __syncthreads();
    }

    #pragma unroll
    for (int mi = 0; mi < 4; mi++) {
        int r0 = mBase + wm * 64 + mi * 16 + (lane >> 2);
        #pragma unroll
        for (int hh = 0; hh < 2; hh++) {
            int r = r0 + hh * 8;
            if (r >= M) continue;
            int x0 = xidx[2 * r], x1 = xidx[2 * r + 1];
            #pragma unroll
            for (int ni = 0; ni < 4; ni++) {
                int c = wn * 32 + ni * 8 + (lane & 3) * 2;
                float v0 = acc[mi][ni][hh * 2 + 0] + bias[c]
                         + label_emb[(size_t)x0 * HIDDEN + c] + type_emb[x1 * HIDDEN + c];
                float v1 = acc[mi][ni][hh * 2 + 1] + bias[c + 1]
                         + label_emb[(size_t)x0 * HIDDEN + c + 1] + type_emb[x1 * HIDDEN + c + 1];
                *(__half2*)(h_out + (size_t)r * HIDDEN + c) = __floats2half2_rn(v0, v1);
                *(float2*)(z_out + (size_t)r * HIDDEN + c) = make_float2(v0, v1);
            }
        }
    }
}

// ---------------------------------------------------------------------------
// Fused MLP: h16 (+z32 if DUAL) = relu(z @ W1 + b1) @ W2 + b2
// t staged in smem fp16 (128x256) — never touches HBM.
// ---------------------------------------------------------------------------
template<bool DUAL>
__global__ void __launch_bounds__(512) fused_mlp(
    const float* __restrict__ Z,
    const float* __restrict__ W1, const float* __restrict__ b1,
    const float* __restrict__ W2, const float* __restrict__ b2,
    __half* __restrict__ h_out, float* __restrict__ z_out, int M)
{
    extern __shared__ __half smem[];
    __half* sT = smem;                           // [BM*ST_STRIDE]
    __half* sA = smem + ST_ELEMS;                // [2][BM*SA_STRIDE]
    __half* sB = smem + ST_ELEMS + SA_ELEMS;     // [2][BK*SB_STRIDE]

    const int tid  = threadIdx.x;
    const int lane = tid & 31;
    const int warp = tid >> 5;
    const int wm   = warp >> 3;
    const int wn   = warp & 7;
    const int mBase = blockIdx.x * BM;

    const int a_row = tid >> 3;
    const int a_col = (tid & 7) << 2;
    const int b_row = tid >> 6;
    const int b_col = (tid & 63) << 2;

    const int KT = HIDDEN / BK;   // 8

    float4 ra[2], rb[4];
    float acc[4][4][4];
    #pragma unroll
    for (int i = 0; i < 4; i++)
        #pragma unroll
        for (int j = 0; j < 4; j++)
            #pragma unroll
            for (int q = 0; q < 4; q++) acc[i][j][q] = 0.f;

    auto ldgA = [&](int kt) {
        #pragma unroll
        for (int i = 0; i < 2; i++) {
            int r = mBase + a_row + i * 64;
            if (r < M) ra[i] = *(const float4*)(Z + (size_t)r * HIDDEN + kt * BK + a_col);
            else       ra[i] = make_float4(0.f, 0.f, 0.f, 0.f);
        }
    };
    auto ldgB = [&](const float* W, int kt) {
        #pragma unroll
        for (int i = 0; i < 4; i++) {
            int r = kt * BK + b_row + i * 8;
            rb[i] = *(const float4*)(W + (size_t)r * HIDDEN + b_col);
        }
    };
    auto stsA = [&](int st) {
        #pragma unroll
        for (int i = 0; i < 2; i++) {
            __half2* p = (__half2*)&sA[st * BM * SA_STRIDE + (a_row + i * 64) * SA_STRIDE + a_col];
            p[0] = __floats2half2_rn(ra[i].x, ra[i].y);
            p[1] = __floats2half2_rn(ra[i].z, ra[i].w);
        }
    };
    auto stsB = [&](int st) {
        #pragma unroll
        for (int i = 0; i < 4; i++) {
            __half2* q = (__half2*)&sB[st * BK * SB_STRIDE + (b_row + i * 8) * SB_STRIDE + b_col];
            q[0] = __floats2half2_rn(rb[i].x, rb[i].y);
            q[1] = __floats2half2_rn(rb[i].z, rb[i].w);
        }
    };

    // ---------------- Stage 1: t = relu(Z @ W1 + b1) -> sT ----------------
    ldgA(0); ldgB(W1, 0); stsA(0); stsB(0); __syncthreads();

    for (int kt = 0; kt < KT; kt++) {
        const int st = kt & 1;
        if (kt + 1 < KT) { ldgA(kt + 1); ldgB(W1, kt + 1); }
        #pragma unroll
        for (int ks = 0; ks < 2; ks++) {
            uint32_t af[4][4], bf[2][4];
            #pragma unroll
            for (int mi = 0; mi < 4; mi++)
                ldsm_x4(af[mi], &sA[st * BM * SA_STRIDE
                         + (wm * 64 + mi * 16 + (lane & 15)) * SA_STRIDE
                         + ks * 16 + (lane >> 4) * 8]);
            #pragma unroll
            for (int p2 = 0; p2 < 2; p2++) {
                int krow = ks * 16 + (lane & 7) + ((lane >> 3) & 1) * 8;
                int ncol = wn * 32 + p2 * 16 + (lane >> 4) * 8;
                ldsm_x4t(bf[p2], &sB[st * BK * SB_STRIDE + krow * SB_STRIDE + ncol]);
            }
            #pragma unroll
            for (int mi = 0; mi < 4; mi++)
                #pragma unroll
                for (int ni = 0; ni < 4; ni++)
                    mma16816(acc[mi][ni], af[mi],
                             bf[ni >> 1][(ni & 1) * 2 + 0], bf[ni >> 1][(ni & 1) * 2 + 1]);
        }
        if (kt + 1 < KT) { stsA(st ^ 1); stsB(st ^ 1); }
        __syncthreads();
    }

    // epilogue 1: relu(+b1) -> sT (fp16), reset acc
    #pragma unroll
    for (int mi = 0; mi < 4; mi++) {
        int rl = wm * 64 + mi * 16 + (lane >> 2);
        #pragma unroll
        for (int hh = 0; hh < 2; hh++) {
            int rr = rl + hh * 8;
            #pragma unroll
            for (int ni = 0; ni < 4; ni++) {
                int c = wn * 32 + ni * 8 + (lane & 3) * 2;
                float v0 = fmaxf(acc[mi][ni][hh * 2 + 0] + b1[c], 0.f);
                float v1 = fmaxf(acc[mi][ni][hh * 2 + 1] + b1[c + 1], 0.f);
                *(__half2*)&sT[rr * ST_STRIDE + c] = __floats2half2_rn(v0, v1);
                acc[mi][ni][hh * 2 + 0] = 0.f;
                acc[mi][ni][hh * 2 + 1] = 0.f;
            }
        }
    }

    // ---------------- Stage 2: out = t @ W2 + b2 ----------------
    ldgB(W2, 0); stsB(0); __syncthreads();

    for (int kt = 0; kt < KT; kt++) {
        const int st = kt & 1;
        if (kt + 1 < KT) ldgB(W2, kt + 1);
        #pragma unroll
        for (int ks = 0; ks < 2; ks++) {
            uint32_t af[4][4], bf[2][4];
            #pragma unroll
            for (int mi = 0; mi < 4; mi++)
                ldsm_x4(af[mi], &sT[(wm * 64 + mi * 16 + (lane & 15)) * ST_STRIDE
                         + kt * BK + ks * 16 + (lane >> 4) * 8]);
            #pragma unroll
            for (int p2 = 0; p2 < 2; p2++) {
                int krow = ks * 16 + (lane & 7) + ((lane >> 3) & 1) * 8;
                int ncol = wn * 32 + p2 * 16 + (lane >> 4) * 8;
                ldsm_x4t(bf[p2], &sB[st * BK * SB_STRIDE + krow * SB_STRIDE + ncol]);
            }
            #pragma unroll
            for (int mi = 0; mi < 4; mi++)
                #pragma unroll
                for (int ni = 0; ni < 4; ni++)
                    mma16816(acc[mi][ni], af[mi],
                             bf[ni >> 1][(ni & 1) * 2 + 0], bf[ni >> 1][(ni & 1) * 2 + 1]);
        }
        if (kt + 1 < KT) stsB(st ^ 1);
        __syncthreads();
    }

    #pragma unroll
    for (int mi = 0; mi < 4; mi++) {
        int r0 = mBase + wm * 64 + mi * 16 + (lane >> 2);
        #pragma unroll
        for (int hh = 0; hh < 2; hh++) {
            int r = r0 + hh * 8;
            if (r >= M) continue;
            #pragma unroll
            for (int ni = 0; ni < 4; ni++) {
                int c = wn * 32 + ni * 8 + (lane & 3) * 2;
                float v0 = acc[mi][ni][hh * 2 + 0] + b2[c];
                float v1 = acc[mi][ni][hh * 2 + 1] + b2[c + 1];
                *(__half2*)(h_out + (size_t)r * HIDDEN + c) = __floats2half2_rn(v0, v1);
                if (DUAL)
                    *(float2*)(z_out + (size_t)r * HIDDEN + c) = make_float2(v0, v1);
            }
        }
    }
}

// ---------------------------------------------------------------------------
// Edge kernel: one warp per edge, h in fp16 (512B rows -> single gather pass)
// ---------------------------------------------------------------------------
__global__ void __launch_bounds__(256) edge_kernel(
    const int*   __restrict__ eattr,
    const int*   __restrict__ eidx,
    const float* __restrict__ role,
    const float* __restrict__ child,
    const __half* __restrict__ h,
    float*       __restrict__ z)
{
    int e = blockIdx.x * 8 + (threadIdx.x >> 5);
    if (e >= N_EDGES) return;
    int lane = threadIdx.x & 31;

    int rrole = __ldg(&eattr[2 * e]);
    int cix   = min(max(__ldg(&eattr[2 * e + 1]), 0), MAX_CHILD - 1);
    int src = __ldg(&eidx[e]);
    int dst = __ldg(&eidx[N_EDGES + e]);

    float4 hv = ((const float4*)(h + (size_t)src * HIDDEN))[lane];  // 8 halves
    const float4* rp = (const float4*)(role + rrole * HIDDEN);
    const float4* cp = (const float4*)(child + cix * HIDDEN);
    float4 r0 = rp[2 * lane], r1 = rp[2 * lane + 1];
    float4 c0 = cp[2 * lane], c1 = cp[2 * lane + 1];

    __half2* hp = (__half2*)&hv;
    float2 f0 = __half22float2(hp[0]);
    float2 f1 = __half22float2(hp[1]);
    float2 f2 = __half22float2(hp[2]);
    float2 f3 = __half22float2(hp[3]);

    float m0 = fmaxf(f0.x + r0.x + c0.x, 0.f);
    float m1 = fmaxf(f0.y + r0.y + c0.y, 0.f);
    float m2 = fmaxf(f1.x + r0.z + c0.z, 0.f);
    float m3 = fmaxf(f1.y + r0.w + c0.w, 0.f);
    float m4 = fmaxf(f2.x + r1.x + c1.x, 0.f);
    float m5 = fmaxf(f2.y + r1.y + c1.y, 0.f);
    float m6 = fmaxf(f3.x + r1.z + c1.z, 0.f);
    float m7 = fmaxf(f3.y + r1.w + c1.w, 0.f);

    float* zd = z + (size_t)dst * HIDDEN + lane * 8;
    asm volatile("red.global.add.v4.f32 [%0], {%1,%2,%3,%4};"
                 :: "l"(zd), "f"(m0), "f"(m1), "f"(m2), "f"(m3) : "memory");
    asm volatile("red.global.add.v4.f32 [%0], {%1,%2,%3,%4};"
                 :: "l"(zd + 4), "f"(m4), "f"(m5), "f"(m6), "f"(m7) : "memory");
}

// ---------------------------------------------------------------------------
// Pool (batch sorted -> binary search), then tiny projection
// ---------------------------------------------------------------------------
__global__ void __launch_bounds__(HIDDEN) pool_kernel(
    const __half* __restrict__ h,
    const int*    __restrict__ batch,
    float*        __restrict__ pooled)
{
    int g = blockIdx.x;
    int t = threadIdx.x;

    int lo = 0, hi = N_NODES;
    while (lo < hi) { int mid = (lo + hi) >> 1; if (batch[mid] < g) lo = mid + 1; else hi = mid; }
    int start = lo;
    hi = N_NODES;
    while (lo < hi) { int mid = (lo + hi) >> 1; if (batch[mid] < g + 1) lo = mid + 1; else hi = mid; }
    int end = lo;

    float acc = 0.f;
    for (int r = start; r < end; r++) acc += __half2float(h[(size_t)r * HIDDEN + t]);
    pooled[g * HIDDEN + t] = acc / fmaxf((float)(end - start), 1.f);
}

__global__ void __launch_bounds__(HIDDEN) proj_kernel(
    const float* __restrict__ pooled,
    const float* __restrict__ W,
    const float* __restrict__ b,
    float*       __restrict__ out)
{
    int g = blockIdx.x;
    int t = threadIdx.x;
    float acc = b[t];
    #pragma unroll 8
    for (int k = 0; k < HIDDEN; k++)
        acc += pooled[g * HIDDEN + k] * W[k * HIDDEN + t];
    out[g * HIDDEN + t] = acc;
}

// ---------------------------------------------------------------------------
extern "C" void kernel_launch(void* const* d_in, const int* in_sizes, int n_in,
                              void* d_out, int out_size)
{
    const int*   x        = (const int*)  d_in[0];
    const float* x_sem    = (const float*)d_in[1];
    const int*   eattr    = (const int*)  d_in[2];
    const int*   eidx     = (const int*)  d_in[3];
    const int*   batch    = (const int*)  d_in[4];
    const float* label    = (const float*)d_in[5];
    const float* type_emb = (const float*)d_in[6];
    const float* sem_W    = (const float*)d_in[7];
    const float* sem_b    = (const float*)d_in[8];
    const float* role     = (const float*)d_in[9];
    const float* child    = (const float*)d_in[10];
    const float* W1_0     = (const float*)d_in[11];
    const float* b1_0     = (const float*)d_in[12];
    const float* W2_0     = (const float*)d_in[13];
    const float* b2_0     = (const float*)d_in[14];
    const float* W1_1     = (const float*)d_in[15];
    const float* b1_1     = (const float*)d_in[16];
    const float* W2_1     = (const float*)d_in[17];
    const float* b2_1     = (const float*)d_in[18];
    const float* proj_W   = (const float*)d_in[19];
    const float* proj_b   = (const float*)d_in[20];
    float* out = (float*)d_out;

    __half* hP; float *zP, *pP;
    cudaGetSymbolAddress((void**)&hP, g_h);
    cudaGetSymbolAddress((void**)&zP, g_z);
    cudaGetSymbolAddress((void**)&pP, g_pool);

    const int embed_smem = (SA_ELEMS + SB_ELEMS) * (int)sizeof(__half);               // ~54 KB
    const int fused_smem = (ST_ELEMS + SA_ELEMS + SB_ELEMS) * (int)sizeof(__half);    // ~122 KB
    cudaFuncSetAttribute(embed_gemm, cudaFuncAttributeMaxDynamicSharedMemorySize, embed_smem);
    cudaFuncSetAttribute(fused_mlp<true>,  cudaFuncAttributeMaxDynamicSharedMemorySize, fused_smem);
    cudaFuncSetAttribute(fused_mlp<false>, cudaFuncAttributeMaxDynamicSharedMemorySize, fused_smem);

    const int gemm_blocks = (N_NODES + BM - 1) / BM;       // 782
    const int edge_blocks = (N_EDGES + 7) / 8;

    // h = label_emb[x0] + type_emb[x1] + x_sem @ sem_W + sem_b ; z = h
    embed_gemm<<<gemm_blocks, 512, embed_smem>>>(
        x_sem, sem_W, sem_b, x, label, type_emb, hP, zP, N_NODES, SEM_IN);

    // GINE layer 0
    edge_kernel<<<edge_blocks, 256>>>(eattr, eidx, role, child, hP, zP);
    fused_mlp<true><<<gemm_blocks, 512, fused_smem>>>(
        zP, W1_0, b1_0, W2_0, b2_0, hP, zP, N_NODES);

    // GINE layer 1
    edge_kernel<<<edge_blocks, 256>>>(eattr, eidx, role, child, hP, zP);
    fused_mlp<false><<<gemm_blocks, 512, fused_smem>>>(
        zP, W1_1, b1_1, W2_1, b2_1, hP, nullptr, N_NODES);

    // pool + projection
    pool_kernel<<<NUM_GRAPHS, HIDDEN>>>(hP, batch, pP);
    proj_kernel<<<NUM_GRAPHS, HIDDEN>>>(pP, proj_W, proj_b, out);
}

// round 3
// speedup vs baseline: 1.2283x; 1.1175x over previous
#include <cuda_runtime.h>
#include <cuda_fp16.h>
#include <stdint.h>

#define N_NODES    100000
#define N_PAD      100096              // padded to 128-row multiple
#define N_EDGES    300000
#define NUM_GRAPHS 128
#define HIDDEN     256
#define SEM_IN     1536
#define MAX_CHILD  200
#define SCAN_B     1024
#define NBLK       ((N_NODES + SCAN_B - 1) / SCAN_B)   // 98

// Scratch (zero-initialized device globals)
__device__ __half g_h[(size_t)N_PAD * HIDDEN];
__device__ __half g_z[(size_t)N_PAD * HIDDEN];
__device__ __half g_w16[SEM_IN * HIDDEN + 4 * HIDDEN * HIDDEN];
__device__ float  g_pool[NUM_GRAPHS * HIDDEN];
__device__ int    g_deg[N_NODES];
__device__ int    g_off[N_NODES];
__device__ int    g_cur[N_NODES];
__device__ int    g_eorder[N_EDGES];
__device__ int    g_bsum[SCAN_B];

#define BM 128
#define BN 256
#define BK 32
#define SA_STRIDE 40
#define SB_STRIDE 264
#define ST_STRIDE 264
#define SA_ELEMS (2 * BM * SA_STRIDE)
#define SB_ELEMS (2 * BK * SB_STRIDE)
#define ST_ELEMS (BM * ST_STRIDE)

// ---------------------------------------------------------------------------
// helpers
// ---------------------------------------------------------------------------
__device__ __forceinline__ void ldsm_x4(uint32_t* r, const __half* p) {
    uint32_t a = (uint32_t)__cvta_generic_to_shared(p);
    asm volatile("ldmatrix.sync.aligned.m8n8.x4.shared.b16 {%0,%1,%2,%3}, [%4];"
                 : "=r"(r[0]), "=r"(r[1]), "=r"(r[2]), "=r"(r[3]) : "r"(a));
}
__device__ __forceinline__ void ldsm_x4t(uint32_t* r, const __half* p) {
    uint32_t a = (uint32_t)__cvta_generic_to_shared(p);
    asm volatile("ldmatrix.sync.aligned.m8n8.x4.trans.shared.b16 {%0,%1,%2,%3}, [%4];"
                 : "=r"(r[0]), "=r"(r[1]), "=r"(r[2]), "=r"(r[3]) : "r"(a));
}
__device__ __forceinline__ void mma16816(float* c, const uint32_t* a,
                                         uint32_t b0, uint32_t b1) {
    asm volatile(
        "mma.sync.aligned.m16n8k16.row.col.f32.f16.f16.f32 "
        "{%0,%1,%2,%3}, {%4,%5,%6,%7}, {%8,%9}, {%0,%1,%2,%3};"
        : "+f"(c[0]), "+f"(c[1]), "+f"(c[2]), "+f"(c[3])
        : "r"(a[0]), "r"(a[1]), "r"(a[2]), "r"(a[3]), "r"(b0), "r"(b1));
}
__device__ __forceinline__ void cp16(__half* smem_dst, const __half* gsrc) {
    uint32_t s = (uint32_t)__cvta_generic_to_shared(smem_dst);
    asm volatile("cp.async.cg.shared.global [%0], [%1], 16;" :: "r"(s), "l"(gsrc));
}
#define CP_COMMIT() asm volatile("cp.async.commit_group;")
#define CP_WAIT0()  asm volatile("cp.async.wait_group 0;")

// ---------------------------------------------------------------------------
// weight fp32 -> fp16 conversion (tiny, once per launch)
// ---------------------------------------------------------------------------
__global__ void cvt_kernel(const float* __restrict__ src, __half* __restrict__ dst, int n) {
    int i = blockIdx.x * blockDim.x + threadIdx.x;
    int e = i * 4;
    if (e < n) {
        float4 v = *(const float4*)(src + e);
        __half2* d = (__half2*)(dst + e);
        d[0] = __floats2half2_rn(v.x, v.y);
        d[1] = __floats2half2_rn(v.z, v.w);
    }
}

// ---------------------------------------------------------------------------
// CSR build
// ---------------------------------------------------------------------------
__global__ void zero_deg_kernel(int* deg) {
    int i = blockIdx.x * blockDim.x + threadIdx.x;
    if (i < N_NODES) deg[i] = 0;
}
__global__ void count_kernel(const int* __restrict__ eidx, int* __restrict__ deg) {
    int e = blockIdx.x * blockDim.x + threadIdx.x;
    if (e < N_EDGES) atomicAdd(&deg[eidx[N_EDGES + e]], 1);
}
__global__ void __launch_bounds__(SCAN_B) scan1_kernel(
    const int* __restrict__ deg, int* __restrict__ off, int* __restrict__ bsum)
{
    __shared__ int s[SCAN_B];
    int tid = threadIdx.x;
    int i = blockIdx.x * SCAN_B + tid;
    int v = (i < N_NODES) ? deg[i] : 0;
    s[tid] = v; __syncthreads();
    #pragma unroll
    for (int d = 1; d < SCAN_B; d <<= 1) {
        int t = (tid >= d) ? s[tid - d] : 0;
        __syncthreads();
        if (tid >= d) s[tid] += t;
        __syncthreads();
    }
    if (i < N_NODES) off[i] = s[tid] - v;           // exclusive
    if (tid == SCAN_B - 1) bsum[blockIdx.x] = s[tid];
}
__global__ void __launch_bounds__(128) scan2_kernel(int* bsum) {
    __shared__ int s[128];
    int tid = threadIdx.x;
    int v = (tid < NBLK) ? bsum[tid] : 0;
    s[tid] = v; __syncthreads();
    #pragma unroll
    for (int d = 1; d < 128; d <<= 1) {
        int t = (tid >= d) ? s[tid - d] : 0;
        __syncthreads();
        if (tid >= d) s[tid] += t;
        __syncthreads();
    }
    if (tid < NBLK) bsum[tid] = s[tid] - v;          // exclusive
}
__global__ void scan3_kernel(int* __restrict__ off, const int* __restrict__ bsum,
                             int* __restrict__ cur) {
    int i = blockIdx.x * blockDim.x + threadIdx.x;
    if (i < N_NODES) {
        int o = off[i] + bsum[i >> 10];
        off[i] = o;
        cur[i] = o;
    }
}
__global__ void scatter_kernel(const int* __restrict__ eidx,
                               int* __restrict__ cur, int* __restrict__ eorder) {
    int e = blockIdx.x * blockDim.x + threadIdx.x;
    if (e < N_EDGES) {
        int pos = atomicAdd(&cur[eidx[N_EDGES + e]], 1);
        eorder[pos] = e;
    }
}

// ---------------------------------------------------------------------------
// Edge aggregation (CSR, atomic-free): one warp per dst node.
// z[n] = h[n] + sum_{e: dst=n} relu(h[src_e] + role[ea0_e] + child[ea1_e])
// ---------------------------------------------------------------------------
__global__ void __launch_bounds__(256) edge_csr_kernel(
    const int*   __restrict__ off,
    const int*   __restrict__ deg,
    const int*   __restrict__ eorder,
    const int*   __restrict__ eattr,
    const int*   __restrict__ eidx,
    const float* __restrict__ role,
    const float* __restrict__ child,
    const __half* __restrict__ h,
    __half*       __restrict__ z)
{
    int n = blockIdx.x * 8 + (threadIdx.x >> 5);
    if (n >= N_NODES) return;
    int lane = threadIdx.x & 31;

    float4 hv = __ldg((const float4*)(h + (size_t)n * HIDDEN) + lane);
    __half2* hp = (__half2*)&hv;
    float2 a0 = __half22float2(hp[0]);
    float2 a1 = __half22float2(hp[1]);
    float2 a2 = __half22float2(hp[2]);
    float2 a3 = __half22float2(hp[3]);
    float acc[8] = {a0.x, a0.y, a1.x, a1.y, a2.x, a2.y, a3.x, a3.y};

    int start = off[n];
    int d = deg[n];
    for (int k = 0; k < d; k++) {
        int e   = __ldg(&eorder[start + k]);
        int src = __ldg(&eidx[e]);
        int r   = __ldg(&eattr[2 * e]);
        int c   = min(max(__ldg(&eattr[2 * e + 1]), 0), MAX_CHILD - 1);

        float4 sv = __ldg((const float4*)(h + (size_t)src * HIDDEN) + lane);
        const float4* rp = (const float4*)(role  + r * HIDDEN) + 2 * lane;
        const float4* cp = (const float4*)(child + c * HIDDEN) + 2 * lane;
        float4 r0 = __ldg(rp), r1 = __ldg(rp + 1);
        float4 c0 = __ldg(cp), c1 = __ldg(cp + 1);

        __half2* sp = (__half2*)&sv;
        float2 f0 = __half22float2(sp[0]);
        float2 f1 = __half22float2(sp[1]);
        float2 f2 = __half22float2(sp[2]);
        float2 f3 = __half22float2(sp[3]);

        acc[0] += fmaxf(f0.x + r0.x + c0.x, 0.f);
        acc[1] += fmaxf(f0.y + r0.y + c0.y, 0.f);
        acc[2] += fmaxf(f1.x + r0.z + c0.z, 0.f);
        acc[3] += fmaxf(f1.y + r0.w + c0.w, 0.f);
        acc[4] += fmaxf(f2.x + r1.x + c1.x, 0.f);
        acc[5] += fmaxf(f2.y + r1.y + c1.y, 0.f);
        acc[6] += fmaxf(f3.x + r1.z + c1.z, 0.f);
        acc[7] += fmaxf(f3.y + r1.w + c1.w, 0.f);
    }

    float4 outv;
    __half2* op = (__half2*)&outv;
    op[0] = __floats2half2_rn(acc[0], acc[1]);
    op[1] = __floats2half2_rn(acc[2], acc[3]);
    op[2] = __floats2half2_rn(acc[4], acc[5]);
    op[3] = __floats2half2_rn(acc[6], acc[7]);
    ((float4*)(z + (size_t)n * HIDDEN))[lane] = outv;
}

// ---------------------------------------------------------------------------
// Embed GEMM: h16 = x_sem(fp32) @ sem_W16 + sem_b + label_emb[x0] + type_emb[x1]
// A reg-staged fp32->fp16; B via cp.async fp16. 512 threads, BM=128, BN=256.
// ---------------------------------------------------------------------------
__global__ void __launch_bounds__(512) embed_gemm(
    const float* __restrict__ A, const __half* __restrict__ B,
    const float* __restrict__ bias,
    const int*   __restrict__ xidx,
    const float* __restrict__ label_emb,
    const float* __restrict__ type_emb,
    __half* __restrict__ h_out, int M, int K)
{
    extern __shared__ __half smem[];
    __half* sA = smem;
    __half* sB = smem + SA_ELEMS;

    const int tid  = threadIdx.x;
    const int lane = tid & 31;
    const int warp = tid >> 5;
    const int wm   = warp >> 3;
    const int wn   = warp & 7;
    const int mBase = blockIdx.x * BM;

    const int a_row = tid >> 3;           // 0..63 (+64)
    const int a_col = (tid & 7) << 2;
    const int b_row = tid >> 4;           // 0..31
    const int b_col = (tid & 15) << 3;    // halves, second chunk at +128

    const int KT = K / BK;

    float4 ra[2];
    float acc[4][4][4];
    #pragma unroll
    for (int i = 0; i < 4; i++)
        #pragma unroll
        for (int j = 0; j < 4; j++)
            #pragma unroll
            for (int q = 0; q < 4; q++) acc[i][j][q] = 0.f;

    auto ldgA = [&](int kt) {
        #pragma unroll
        for (int i = 0; i < 2; i++) {
            int r = mBase + a_row + i * 64;
            if (r < M) ra[i] = *(const float4*)(A + (size_t)r * K + kt * BK + a_col);
            else       ra[i] = make_float4(0.f, 0.f, 0.f, 0.f);
        }
    };
    auto stsA = [&](int st) {
        #pragma unroll
        for (int i = 0; i < 2; i++) {
            __half2* p = (__half2*)&sA[st * BM * SA_STRIDE + (a_row + i * 64) * SA_STRIDE + a_col];
            p[0] = __floats2half2_rn(ra[i].x, ra[i].y);
            p[1] = __floats2half2_rn(ra[i].z, ra[i].w);
        }
    };
    auto cpB = [&](int kt, int st) {
        const __half* g = B + (size_t)(kt * BK + b_row) * HIDDEN + b_col;
        __half* s = &sB[st * BK * SB_STRIDE + b_row * SB_STRIDE + b_col];
        cp16(s, g);
        cp16(s + 128, g + 128);
    };

    ldgA(0); cpB(0, 0); CP_COMMIT();
    stsA(0); CP_WAIT0(); __syncthreads();

    for (int kt = 0; kt < KT; kt++) {
        const int st = kt & 1;
        if (kt + 1 < KT) { ldgA(kt + 1); cpB(kt + 1, st ^ 1); CP_COMMIT(); }
        #pragma unroll
        for (int ks = 0; ks < 2; ks++) {
            uint32_t af[4][4], bf[2][4];
            #pragma unroll
            for (int mi = 0; mi < 4; mi++)
                ldsm_x4(af[mi], &sA[st * BM * SA_STRIDE
                         + (wm * 64 + mi * 16 + (lane & 15)) * SA_STRIDE
                         + ks * 16 + (lane >> 4) * 8]);
            #pragma unroll
            for (int p2 = 0; p2 < 2; p2++) {
                int krow = ks * 16 + (lane & 7) + ((lane >> 3) & 1) * 8;
                int ncol = wn * 32 + p2 * 16 + (lane >> 4) * 8;
                ldsm_x4t(bf[p2], &sB[st * BK * SB_STRIDE + krow * SB_STRIDE + ncol]);
            }
            #pragma unroll
            for (int mi = 0; mi < 4; mi++)
                #pragma unroll
                for (int ni = 0; ni < 4; ni++)
                    mma16816(acc[mi][ni], af[mi],
                             bf[ni >> 1][(ni & 1) * 2 + 0], bf[ni >> 1][(ni & 1) * 2 + 1]);
        }
        if (kt + 1 < KT) { stsA(st ^ 1); CP_WAIT0(); }
        __syncthreads();
    }

    #pragma unroll
    for (int mi = 0; mi < 4; mi++) {
        int r0 = mBase + wm * 64 + mi * 16 + (lane >> 2);
        #pragma unroll
        for (int hh = 0; hh < 2; hh++) {
            int r = r0 + hh * 8;
            if (r >= M) continue;
            int x0 = xidx[2 * r], x1 = xidx[2 * r + 1];
            #pragma unroll
            for (int ni = 0; ni < 4; ni++) {
                int c = wn * 32 + ni * 8 + (lane & 3) * 2;
                float v0 = acc[mi][ni][hh * 2 + 0] + bias[c]
                         + label_emb[(size_t)x0 * HIDDEN + c] + type_emb[x1 * HIDDEN + c];
                float v1 = acc[mi][ni][hh * 2 + 1] + bias[c + 1]
                         + label_emb[(size_t)x0 * HIDDEN + c + 1] + type_emb[x1 * HIDDEN + c + 1];
                *(__half2*)(h_out + (size_t)r * HIDDEN + c) = __floats2half2_rn(v0, v1);
            }
        }
    }
}

// ---------------------------------------------------------------------------
// Fused MLP: h16 = relu(z16 @ W1_16 + b1) @ W2_16 + b2
// z padded to N_PAD rows (pad rows are zero) -> unguarded cp.async loads.
// ---------------------------------------------------------------------------
__global__ void __launch_bounds__(512) fused_mlp(
    const __half* __restrict__ Z,
    const __half* __restrict__ W1, const float* __restrict__ b1,
    const __half* __restrict__ W2, const float* __restrict__ b2,
    __half* __restrict__ h_out, int M)
{
    extern __shared__ __half smem[];
    __half* sT = smem;
    __half* sA = smem + ST_ELEMS;
    __half* sB = smem + ST_ELEMS + SA_ELEMS;

    const int tid  = threadIdx.x;
    const int lane = tid & 31;
    const int warp = tid >> 5;
    const int wm   = warp >> 3;
    const int wn   = warp & 7;
    const int mBase = blockIdx.x * BM;

    const int a_row = tid >> 2;           // 0..127
    const int a_col = (tid & 3) << 3;     // halves
    const int b_row = tid >> 4;
    const int b_col = (tid & 15) << 3;

    const int KT = HIDDEN / BK;           // 8

    float acc[4][4][4];
    #pragma unroll
    for (int i = 0; i < 4; i++)
        #pragma unroll
        for (int j = 0; j < 4; j++)
            #pragma unroll
            for (int q = 0; q < 4; q++) acc[i][j][q] = 0.f;

    auto cpA = [&](int kt, int st) {
        cp16(&sA[st * BM * SA_STRIDE + a_row * SA_STRIDE + a_col],
             Z + (size_t)(mBase + a_row) * HIDDEN + kt * BK + a_col);
    };
    auto cpB = [&](const __half* W, int kt, int st) {
        const __half* g = W + (size_t)(kt * BK + b_row) * HIDDEN + b_col;
        __half* s = &sB[st * BK * SB_STRIDE + b_row * SB_STRIDE + b_col];
        cp16(s, g);
        cp16(s + 128, g + 128);
    };

    auto compute = [&](const __half* aBase, int aStride, int aColOff, int st) {
        #pragma unroll
        for (int ks = 0; ks < 2; ks++) {
            uint32_t af[4][4], bf[2][4];
            #pragma unroll
            for (int mi = 0; mi < 4; mi++)
                ldsm_x4(af[mi], aBase
                         + (wm * 64 + mi * 16 + (lane & 15)) * aStride
                         + aColOff + ks * 16 + (lane >> 4) * 8);
            #pragma unroll
            for (int p2 = 0; p2 < 2; p2++) {
                int krow = ks * 16 + (lane & 7) + ((lane >> 3) & 1) * 8;
                int ncol = wn * 32 + p2 * 16 + (lane >> 4) * 8;
                ldsm_x4t(bf[p2], &sB[st * BK * SB_STRIDE + krow * SB_STRIDE + ncol]);
            }
            #pragma unroll
            for (int mi = 0; mi < 4; mi++)
                #pragma unroll
                for (int ni = 0; ni < 4; ni++)
                    mma16816(acc[mi][ni], af[mi],
                             bf[ni >> 1][(ni & 1) * 2 + 0], bf[ni >> 1][(ni & 1) * 2 + 1]);
        }
    };

    // ---- Stage 1: t = relu(Z @ W1 + b1) -> sT ----
    cpA(0, 0); cpB(W1, 0, 0); CP_COMMIT(); CP_WAIT0(); __syncthreads();
    for (int kt = 0; kt < KT; kt++) {
        const int st = kt & 1;
        if (kt + 1 < KT) { cpA(kt + 1, st ^ 1); cpB(W1, kt + 1, st ^ 1); CP_COMMIT(); }
        compute(&sA[st * BM * SA_STRIDE], SA_STRIDE, 0, st);
        if (kt + 1 < KT) CP_WAIT0();
        __syncthreads();
    }

    #pragma unroll
    for (int mi = 0; mi < 4; mi++) {
        int rl = wm * 64 + mi * 16 + (lane >> 2);
        #pragma unroll
        for (int hh = 0; hh < 2; hh++) {
            int rr = rl + hh * 8;
            #pragma unroll
            for (int ni = 0; ni < 4; ni++) {
                int c = wn * 32 + ni * 8 + (lane & 3) * 2;
                float v0 = fmaxf(acc[mi][ni][hh * 2 + 0] + b1[c], 0.f);
                float v1 = fmaxf(acc[mi][ni][hh * 2 + 1] + b1[c + 1], 0.f);
                *(__half2*)&sT[rr * ST_STRIDE + c] = __floats2half2_rn(v0, v1);
                acc[mi][ni][hh * 2 + 0] = 0.f;
                acc[mi][ni][hh * 2 + 1] = 0.f;
            }
        }
    }

    // ---- Stage 2: out = t @ W2 + b2 ----
    cpB(W2, 0, 0); CP_COMMIT(); CP_WAIT0(); __syncthreads();
    for (int kt = 0; kt < KT; kt++) {
        const int st = kt & 1;
        if (kt + 1 < KT) { cpB(W2, kt + 1, st ^ 1); CP_COMMIT(); }
        compute(sT, ST_STRIDE, kt * BK, st);
        if (kt + 1 < KT) CP_WAIT0();
        __syncthreads();
    }

    #pragma unroll
    for (int mi = 0; mi < 4; mi++) {
        int r0 = mBase + wm * 64 + mi * 16 + (lane >> 2);
        #pragma unroll
        for (int hh = 0; hh < 2; hh++) {
            int r = r0 + hh * 8;
            if (r >= M) continue;
            #pragma unroll
            for (int ni = 0; ni < 4; ni++) {
                int c = wn * 32 + ni * 8 + (lane & 3) * 2;
                float v0 = acc[mi][ni][hh * 2 + 0] + b2[c];
                float v1 = acc[mi][ni][hh * 2 + 1] + b2[c + 1];
                *(__half2*)(h_out + (size_t)r * HIDDEN + c) = __floats2half2_rn(v0, v1);
            }
        }
    }
}

// ---------------------------------------------------------------------------
// Pool + projection
// ---------------------------------------------------------------------------
__global__ void __launch_bounds__(HIDDEN) pool_kernel(
    const __half* __restrict__ h,
    const int*    __restrict__ batch,
    float*        __restrict__ pooled)
{
    int g = blockIdx.x;
    int t = threadIdx.x;

    int lo = 0, hi = N_NODES;
    while (lo < hi) { int mid = (lo + hi) >> 1; if (batch[mid] < g) lo = mid + 1; else hi = mid; }
    int start = lo;
    hi = N_NODES;
    while (lo < hi) { int mid = (lo + hi) >> 1; if (batch[mid] < g + 1) lo = mid + 1; else hi = mid; }
    int end = lo;

    float acc = 0.f;
    for (int r = start; r < end; r++) acc += __half2float(h[(size_t)r * HIDDEN + t]);
    pooled[g * HIDDEN + t] = acc / fmaxf((float)(end - start), 1.f);
}

__global__ void __launch_bounds__(HIDDEN) proj_kernel(
    const float* __restrict__ pooled,
    const float* __restrict__ W,
    const float* __restrict__ b,
    float*       __restrict__ out)
{
    int g = blockIdx.x;
    int t = threadIdx.x;
    float acc = b[t];
    #pragma unroll 8
    for (int k = 0; k < HIDDEN; k++)
        acc += pooled[g * HIDDEN + k] * W[k * HIDDEN + t];
    out[g * HIDDEN + t] = acc;
}

// ---------------------------------------------------------------------------
extern "C" void kernel_launch(void* const* d_in, const int* in_sizes, int n_in,
                              void* d_out, int out_size)
{
    const int*   x        = (const int*)  d_in[0];
    const float* x_sem    = (const float*)d_in[1];
    const int*   eattr    = (const int*)  d_in[2];
    const int*   eidx     = (const int*)  d_in[3];
    const int*   batch    = (const int*)  d_in[4];
    const float* label    = (const float*)d_in[5];
    const float* type_emb = (const float*)d_in[6];
    const float* sem_W    = (const float*)d_in[7];
    const float* sem_b    = (const float*)d_in[8];
    const float* role     = (const float*)d_in[9];
    const float* child    = (const float*)d_in[10];
    const float* W1_0     = (const float*)d_in[11];
    const float* b1_0     = (const float*)d_in[12];
    const float* W2_0     = (const float*)d_in[13];
    const float* b2_0     = (const float*)d_in[14];
    const float* W1_1     = (const float*)d_in[15];
    const float* b1_1     = (const float*)d_in[16];
    const float* W2_1     = (const float*)d_in[17];
    const float* b2_1     = (const float*)d_in[18];
    const float* proj_W   = (const float*)d_in[19];
    const float* proj_b   = (const float*)d_in[20];
    float* out = (float*)d_out;

    __half *hP, *zP, *wP;
    float *pP;
    int *degP, *offP, *curP, *eoP, *bsP;
    cudaGetSymbolAddress((void**)&hP, g_h);
    cudaGetSymbolAddress((void**)&zP, g_z);
    cudaGetSymbolAddress((void**)&wP, g_w16);
    cudaGetSymbolAddress((void**)&pP, g_pool);
    cudaGetSymbolAddress((void**)&degP, g_deg);
    cudaGetSymbolAddress((void**)&offP, g_off);
    cudaGetSymbolAddress((void**)&curP, g_cur);
    cudaGetSymbolAddress((void**)&eoP, g_eorder);
    cudaGetSymbolAddress((void**)&bsP, g_bsum);

    __half* w_sem = wP;
    __half* w1_0  = wP + SEM_IN * HIDDEN;
    __half* w2_0  = w1_0 + HIDDEN * HIDDEN;
    __half* w1_1  = w2_0 + HIDDEN * HIDDEN;
    __half* w2_1  = w1_1 + HIDDEN * HIDDEN;

    const int embed_smem = (SA_ELEMS + SB_ELEMS) * (int)sizeof(__half);
    const int fused_smem = (ST_ELEMS + SA_ELEMS + SB_ELEMS) * (int)sizeof(__half);
    cudaFuncSetAttribute(embed_gemm, cudaFuncAttributeMaxDynamicSharedMemorySize, embed_smem);
    cudaFuncSetAttribute(fused_mlp,  cudaFuncAttributeMaxDynamicSharedMemorySize, fused_smem);

    // weights -> fp16 (tiny)
    cvt_kernel<<<(SEM_IN * HIDDEN / 4 + 255) / 256, 256>>>(sem_W, w_sem, SEM_IN * HIDDEN);
    cvt_kernel<<<(HIDDEN * HIDDEN / 4 + 255) / 256, 256>>>(W1_0, w1_0, HIDDEN * HIDDEN);
    cvt_kernel<<<(HIDDEN * HIDDEN / 4 + 255) / 256, 256>>>(W2_0, w2_0, HIDDEN * HIDDEN);
    cvt_kernel<<<(HIDDEN * HIDDEN / 4 + 255) / 256, 256>>>(W1_1, w1_1, HIDDEN * HIDDEN);
    cvt_kernel<<<(HIDDEN * HIDDEN / 4 + 255) / 256, 256>>>(W2_1, w2_1, HIDDEN * HIDDEN);

    // CSR build (graph static across layers)
    zero_deg_kernel<<<(N_NODES + 255) / 256, 256>>>(degP);
    count_kernel<<<(N_EDGES + 255) / 256, 256>>>(eidx, degP);
    scan1_kernel<<<NBLK, SCAN_B>>>(degP, offP, bsP);
    scan2_kernel<<<1, 128>>>(bsP);
    scan3_kernel<<<(N_NODES + 255) / 256, 256>>>(offP, bsP, curP);
    scatter_kernel<<<(N_EDGES + 255) / 256, 256>>>(eidx, curP, eoP);

    const int gemm_blocks = (N_NODES + BM - 1) / BM;   // 782
    const int node_blocks = (N_NODES + 7) / 8;

    // embed
    embed_gemm<<<gemm_blocks, 512, embed_smem>>>(
        x_sem, w_sem, sem_b, x, label, type_emb, hP, N_NODES, SEM_IN);

    // GINE layer 0
    edge_csr_kernel<<<node_blocks, 256>>>(offP, degP, eoP, eattr, eidx, role, child, hP, zP);
    fused_mlp<<<gemm_blocks, 512, fused_smem>>>(zP, w1_0, b1_0, w2_0, b2_0, hP, N_NODES);

    // GINE layer 1
    edge_csr_kernel<<<node_blocks, 256>>>(offP, degP, eoP, eattr, eidx, role, child, hP, zP);
    fused_mlp<<<gemm_blocks, 512, fused_smem>>>(zP, w1_1, b1_1, w2_1, b2_1, hP, N_NODES);

    // pool + projection
    pool_kernel<<<NUM_GRAPHS, HIDDEN>>>(hP, batch, pP);
    proj_kernel<<<NUM_GRAPHS, HIDDEN>>>(pP, proj_W, proj_b, out);
}

// round 5
// speedup vs baseline: 1.2928x; 1.0525x over previous
#include <cuda_runtime.h>
#include <cuda_fp16.h>
#include <stdint.h>

#define N_NODES    100000
#define N_PAD      100096
#define N_EDGES    300000
#define NUM_GRAPHS 128
#define HIDDEN     256
#define SEM_IN     1536
#define MAX_CHILD  200
#define N_COMBO    (8 * MAX_CHILD)
#define SCAN_B     1024
#define NBLK       ((N_NODES + SCAN_B - 1) / SCAN_B)   // 98

// Scratch (zero-initialized device globals)
__device__ __align__(16) __half g_h[(size_t)N_PAD * HIDDEN];
__device__ __align__(16) __half g_z[(size_t)N_PAD * HIDDEN];
__device__ __align__(16) __half g_w16[SEM_IN * HIDDEN + 4 * HIDDEN * HIDDEN];
__device__ __align__(16) __half g_combo[(size_t)N_COMBO * HIDDEN];
__device__ float  g_pool[NUM_GRAPHS * HIDDEN];
__device__ int    g_deg[N_NODES];
__device__ int    g_off[N_NODES];
__device__ int    g_cur[N_NODES];
__device__ int    g_csr_src[N_EDGES];
__device__ int    g_csr_cid[N_EDGES];
__device__ int    g_bsum[SCAN_B];

#define BM 128
#define BK 32
#define SA_STRIDE 40
#define SB_STRIDE 264
#define ST_STRIDE 264
#define SA_ELEMS (2 * BM * SA_STRIDE)
#define SB_ELEMS (2 * BK * SB_STRIDE)
#define ST_ELEMS (BM * ST_STRIDE)

// ---------------------------------------------------------------------------
// helpers
// ---------------------------------------------------------------------------
__device__ __forceinline__ void ldsm_x4(uint32_t* r, const __half* p) {
    uint32_t a = (uint32_t)__cvta_generic_to_shared(p);
    asm volatile("ldmatrix.sync.aligned.m8n8.x4.shared.b16 {%0,%1,%2,%3}, [%4];"
                 : "=r"(r[0]), "=r"(r[1]), "=r"(r[2]), "=r"(r[3]) : "r"(a));
}
__device__ __forceinline__ void ldsm_x4t(uint32_t* r, const __half* p) {
    uint32_t a = (uint32_t)__cvta_generic_to_shared(p);
    asm volatile("ldmatrix.sync.aligned.m8n8.x4.trans.shared.b16 {%0,%1,%2,%3}, [%4];"
                 : "=r"(r[0]), "=r"(r[1]), "=r"(r[2]), "=r"(r[3]) : "r"(a));
}
__device__ __forceinline__ void mma16816(float* c, const uint32_t* a,
                                         uint32_t b0, uint32_t b1) {
    asm volatile(
        "mma.sync.aligned.m16n8k16.row.col.f32.f16.f16.f32 "
        "{%0,%1,%2,%3}, {%4,%5,%6,%7}, {%8,%9}, {%0,%1,%2,%3};"
        : "+f"(c[0]), "+f"(c[1]), "+f"(c[2]), "+f"(c[3])
        : "r"(a[0]), "r"(a[1]), "r"(a[2]), "r"(a[3]), "r"(b0), "r"(b1));
}
__device__ __forceinline__ void cp16(void* smem_dst, const void* gsrc) {
    uint32_t s = (uint32_t)__cvta_generic_to_shared(smem_dst);
    asm volatile("cp.async.cg.shared.global [%0], [%1], 16;" :: "r"(s), "l"(gsrc));
}
#define CP_COMMIT() asm volatile("cp.async.commit_group;")
#define CP_WAIT0()  asm volatile("cp.async.wait_group 0;")

// ---------------------------------------------------------------------------
// setup kernels
// ---------------------------------------------------------------------------
__global__ void cvt_kernel(const float* __restrict__ src, __half* __restrict__ dst, int n) {
    int e = (blockIdx.x * blockDim.x + threadIdx.x) * 4;
    if (e < n) {
        float4 v = *(const float4*)(src + e);
        __half2* d = (__half2*)(dst + e);
        d[0] = __floats2half2_rn(v.x, v.y);
        d[1] = __floats2half2_rn(v.z, v.w);
    }
}
__global__ void combo_kernel(const float* __restrict__ role, const float* __restrict__ child,
                             __half* __restrict__ combo) {
    int rc = blockIdx.x;
    int r = rc / MAX_CHILD, cc = rc % MAX_CHILD;
    int t = threadIdx.x;                      // 128
    float2 a = *(const float2*)(role + r * HIDDEN + t * 2);
    float2 b = *(const float2*)(child + cc * HIDDEN + t * 2);
    *(__half2*)(combo + (size_t)rc * HIDDEN + t * 2) = __floats2half2_rn(a.x + b.x, a.y + b.y);
}

// ---------------------------------------------------------------------------
// CSR build
// ---------------------------------------------------------------------------
__global__ void zero_deg_kernel(int* deg) {
    int i = blockIdx.x * blockDim.x + threadIdx.x;
    if (i < N_NODES) deg[i] = 0;
}
__global__ void count_kernel(const int* __restrict__ eidx, int* __restrict__ deg) {
    int e = blockIdx.x * blockDim.x + threadIdx.x;
    if (e < N_EDGES) atomicAdd(&deg[eidx[N_EDGES + e]], 1);
}
__global__ void __launch_bounds__(SCAN_B) scan1_kernel(
    const int* __restrict__ deg, int* __restrict__ off, int* __restrict__ bsum)
{
    __shared__ int s[SCAN_B];
    int tid = threadIdx.x;
    int i = blockIdx.x * SCAN_B + tid;
    int v = (i < N_NODES) ? deg[i] : 0;
    s[tid] = v; __syncthreads();
    #pragma unroll
    for (int d = 1; d < SCAN_B; d <<= 1) {
        int t = (tid >= d) ? s[tid - d] : 0;
        __syncthreads();
        if (tid >= d) s[tid] += t;
        __syncthreads();
    }
    if (i < N_NODES) off[i] = s[tid] - v;
    if (tid == SCAN_B - 1) bsum[blockIdx.x] = s[tid];
}
__global__ void __launch_bounds__(128) scan2_kernel(int* bsum) {
    __shared__ int s[128];
    int tid = threadIdx.x;
    int v = (tid < NBLK) ? bsum[tid] : 0;
    s[tid] = v; __syncthreads();
    #pragma unroll
    for (int d = 1; d < 128; d <<= 1) {
        int t = (tid >= d) ? s[tid - d] : 0;
        __syncthreads();
        if (tid >= d) s[tid] += t;
        __syncthreads();
    }
    if (tid < NBLK) bsum[tid] = s[tid] - v;
}
__global__ void scan3_kernel(int* __restrict__ off, const int* __restrict__ bsum,
                             int* __restrict__ cur) {
    int i = blockIdx.x * blockDim.x + threadIdx.x;
    if (i < N_NODES) {
        int o = off[i] + bsum[i >> 10];
        off[i] = o;
        cur[i] = o;
    }
}
__global__ void scatter_kernel(const int* __restrict__ eidx, const int* __restrict__ eattr,
                               int* __restrict__ cur,
                               int* __restrict__ csr_src, int* __restrict__ csr_cid) {
    int e = blockIdx.x * blockDim.x + threadIdx.x;
    if (e < N_EDGES) {
        int pos = atomicAdd(&cur[eidx[N_EDGES + e]], 1);
        csr_src[pos] = eidx[e];
        int r  = eattr[2 * e];
        int cc = min(max(eattr[2 * e + 1], 0), MAX_CHILD - 1);
        csr_cid[pos] = r * MAX_CHILD + cc;
    }
}

// ---------------------------------------------------------------------------
// Edge aggregation (CSR, atomic-free, fp16 combo table): one warp per dst node.
// z[n] = h[n] + sum_e relu(h[src_e] + combo[cid_e])
// ---------------------------------------------------------------------------
__global__ void __launch_bounds__(256) edge_csr_kernel(
    const int*    __restrict__ off,
    const int*    __restrict__ deg,
    const int*    __restrict__ csr_src,
    const int*    __restrict__ csr_cid,
    const __half* __restrict__ combo,
    const __half* __restrict__ h,
    __half*       __restrict__ z)
{
    int n = blockIdx.x * 8 + (threadIdx.x >> 5);
    if (n >= N_NODES) return;
    int lane = threadIdx.x & 31;

    float4 hv = __ldg((const float4*)(h + (size_t)n * HIDDEN) + lane);
    __half2* hp = (__half2*)&hv;
    float2 a0 = __half22float2(hp[0]), a1 = __half22float2(hp[1]);
    float2 a2 = __half22float2(hp[2]), a3 = __half22float2(hp[3]);
    float acc[8] = {a0.x, a0.y, a1.x, a1.y, a2.x, a2.y, a3.x, a3.y};

    int start = off[n];
    int d = deg[n];
    for (int k = 0; k < d; k++) {
        int s   = __ldg(&csr_src[start + k]);
        int cid = __ldg(&csr_cid[start + k]);
        float4 sv = __ldg((const float4*)(h + (size_t)s * HIDDEN) + lane);
        float4 cv = __ldg((const float4*)(combo + (size_t)cid * HIDDEN) + lane);
        __half2* sp = (__half2*)&sv;
        __half2* cp = (__half2*)&cv;
        #pragma unroll
        for (int j = 0; j < 4; j++) {
            float2 f = __half22float2(sp[j]);
            float2 c = __half22float2(cp[j]);
            acc[2 * j + 0] += fmaxf(f.x + c.x, 0.f);
            acc[2 * j + 1] += fmaxf(f.y + c.y, 0.f);
        }
    }

    float4 outv;
    __half2* op = (__half2*)&outv;
    op[0] = __floats2half2_rn(acc[0], acc[1]);
    op[1] = __floats2half2_rn(acc[2], acc[3]);
    op[2] = __floats2half2_rn(acc[4], acc[5]);
    op[3] = __floats2half2_rn(acc[6], acc[7]);
    ((float4*)(z + (size_t)n * HIDDEN))[lane] = outv;
}

// ---------------------------------------------------------------------------
// Embed GEMM (mma.sync): h16 = x_sem(fp32)@sem_W16 + sem_b + label[x0] + type[x1]
// BM=128, BN=256, BK=32, 512 threads; A reg-staged fp32->fp16; B cp.async fp16.
// ---------------------------------------------------------------------------
__global__ void __launch_bounds__(512) embed_gemm(
    const float* __restrict__ A, const __half* __restrict__ B,
    const float* __restrict__ bias,
    const int*   __restrict__ xidx,
    const float* __restrict__ label_emb,
    const float* __restrict__ type_emb,
    __half* __restrict__ h_out, int M, int K)
{
    extern __shared__ __half smem[];
    __half* sA = smem;
    __half* sB = smem + SA_ELEMS;

    const int tid  = threadIdx.x;
    const int lane = tid & 31;
    const int warp = tid >> 5;
    const int wm   = warp >> 3;
    const int wn   = warp & 7;
    const int mBase = blockIdx.x * BM;

    const int a_row = tid >> 3;           // 0..63 (+64)
    const int a_col = (tid & 7) << 2;
    const int b_row = tid >> 4;           // 0..31
    const int b_col = (tid & 15) << 3;    // halves, second chunk at +128

    const int KT = K / BK;

    float4 ra[2];
    float acc[4][4][4];
    #pragma unroll
    for (int i = 0; i < 4; i++)
        #pragma unroll
        for (int j = 0; j < 4; j++)
            #pragma unroll
            for (int q = 0; q < 4; q++) acc[i][j][q] = 0.f;

    auto ldgA = [&](int kt) {
        #pragma unroll
        for (int i = 0; i < 2; i++) {
            int r = mBase + a_row + i * 64;
            if (r < M) ra[i] = *(const float4*)(A + (size_t)r * K + kt * BK + a_col);
            else       ra[i] = make_float4(0.f, 0.f, 0.f, 0.f);
        }
    };
    auto stsA = [&](int st) {
        #pragma unroll
        for (int i = 0; i < 2; i++) {
            __half2* p = (__half2*)&sA[st * BM * SA_STRIDE + (a_row + i * 64) * SA_STRIDE + a_col];
            p[0] = __floats2half2_rn(ra[i].x, ra[i].y);
            p[1] = __floats2half2_rn(ra[i].z, ra[i].w);
        }
    };
    auto cpB = [&](int kt, int st) {
        const __half* g = B + (size_t)(kt * BK + b_row) * HIDDEN + b_col;
        __half* s = &sB[st * BK * SB_STRIDE + b_row * SB_STRIDE + b_col];
        cp16(s, g);
        cp16(s + 128, g + 128);
    };

    ldgA(0); cpB(0, 0); CP_COMMIT();
    stsA(0); CP_WAIT0(); __syncthreads();

    for (int kt = 0; kt < KT; kt++) {
        const int st = kt & 1;
        if (kt + 1 < KT) { ldgA(kt + 1); cpB(kt + 1, st ^ 1); CP_COMMIT(); }
        #pragma unroll
        for (int ks = 0; ks < 2; ks++) {
            uint32_t af[4][4], bf[2][4];
            #pragma unroll
            for (int mi = 0; mi < 4; mi++)
                ldsm_x4(af[mi], &sA[st * BM * SA_STRIDE
                         + (wm * 64 + mi * 16 + (lane & 15)) * SA_STRIDE
                         + ks * 16 + (lane >> 4) * 8]);
            #pragma unroll
            for (int p2 = 0; p2 < 2; p2++) {
                int krow = ks * 16 + (lane & 7) + ((lane >> 3) & 1) * 8;
                int ncol = wn * 32 + p2 * 16 + (lane >> 4) * 8;
                ldsm_x4t(bf[p2], &sB[st * BK * SB_STRIDE + krow * SB_STRIDE + ncol]);
            }
            #pragma unroll
            for (int mi = 0; mi < 4; mi++)
                #pragma unroll
                for (int ni = 0; ni < 4; ni++)
                    mma16816(acc[mi][ni], af[mi],
                             bf[ni >> 1][(ni & 1) * 2 + 0], bf[ni >> 1][(ni & 1) * 2 + 1]);
        }
        if (kt + 1 < KT) { stsA(st ^ 1); CP_WAIT0(); }
        __syncthreads();
    }

    #pragma unroll
    for (int mi = 0; mi < 4; mi++) {
        int r0 = mBase + wm * 64 + mi * 16 + (lane >> 2);
        #pragma unroll
        for (int hh = 0; hh < 2; hh++) {
            int r = r0 + hh * 8;
            if (r >= M) continue;
            int x0 = xidx[2 * r], x1 = xidx[2 * r + 1];
            #pragma unroll
            for (int ni = 0; ni < 4; ni++) {
                int c = wn * 32 + ni * 8 + (lane & 3) * 2;
                float v0 = acc[mi][ni][hh * 2 + 0] + bias[c]
                         + label_emb[(size_t)x0 * HIDDEN + c] + type_emb[x1 * HIDDEN + c];
                float v1 = acc[mi][ni][hh * 2 + 1] + bias[c + 1]
                         + label_emb[(size_t)x0 * HIDDEN + c + 1] + type_emb[x1 * HIDDEN + c + 1];
                *(__half2*)(h_out + (size_t)r * HIDDEN + c) = __floats2half2_rn(v0, v1);
            }
        }
    }
}

// ---------------------------------------------------------------------------
// Fused MLP: h16 = relu(z16 @ W1_16 + b1) @ W2_16 + b2 (t staged in smem)
// ---------------------------------------------------------------------------
__global__ void __launch_bounds__(512) fused_mlp(
    const __half* __restrict__ Z,
    const __half* __restrict__ W1, const float* __restrict__ b1,
    const __half* __restrict__ W2, const float* __restrict__ b2,
    __half* __restrict__ h_out, int M)
{
    extern __shared__ __half hsm[];
    __half* sT = hsm;
    __half* sA = hsm + ST_ELEMS;
    __half* sB = hsm + ST_ELEMS + SA_ELEMS;

    const int tid  = threadIdx.x;
    const int lane = tid & 31;
    const int warp = tid >> 5;
    const int wm   = warp >> 3;
    const int wn   = warp & 7;
    const int mBase = blockIdx.x * BM;

    const int a_row = tid >> 2;
    const int a_col = (tid & 3) << 3;
    const int b_row = tid >> 4;
    const int b_col = (tid & 15) << 3;

    const int KT = HIDDEN / BK;

    float acc[4][4][4];
    #pragma unroll
    for (int i = 0; i < 4; i++)
        #pragma unroll
        for (int j = 0; j < 4; j++)
            #pragma unroll
            for (int q = 0; q < 4; q++) acc[i][j][q] = 0.f;

    auto cpA = [&](int kt, int st) {
        cp16(&sA[st * BM * SA_STRIDE + a_row * SA_STRIDE + a_col],
             Z + (size_t)(mBase + a_row) * HIDDEN + kt * BK + a_col);
    };
    auto cpB = [&](const __half* W, int kt, int st) {
        const __half* g = W + (size_t)(kt * BK + b_row) * HIDDEN + b_col;
        __half* s = &sB[st * BK * SB_STRIDE + b_row * SB_STRIDE + b_col];
        cp16(s, g);
        cp16(s + 128, g + 128);
    };
    auto compute = [&](const __half* aBase, int aStride, int aColOff, int st) {
        #pragma unroll
        for (int ks = 0; ks < 2; ks++) {
            uint32_t af[4][4], bf[2][4];
            #pragma unroll
            for (int mi = 0; mi < 4; mi++)
                ldsm_x4(af[mi], aBase
                         + (wm * 64 + mi * 16 + (lane & 15)) * aStride
                         + aColOff + ks * 16 + (lane >> 4) * 8);
            #pragma unroll
            for (int p2 = 0; p2 < 2; p2++) {
                int krow = ks * 16 + (lane & 7) + ((lane >> 3) & 1) * 8;
                int ncol = wn * 32 + p2 * 16 + (lane >> 4) * 8;
                ldsm_x4t(bf[p2], &sB[st * BK * SB_STRIDE + krow * SB_STRIDE + ncol]);
            }
            #pragma unroll
            for (int mi = 0; mi < 4; mi++)
                #pragma unroll
                for (int ni = 0; ni < 4; ni++)
                    mma16816(acc[mi][ni], af[mi],
                             bf[ni >> 1][(ni & 1) * 2 + 0], bf[ni >> 1][(ni & 1) * 2 + 1]);
        }
    };

    cpA(0, 0); cpB(W1, 0, 0); CP_COMMIT(); CP_WAIT0(); __syncthreads();
    for (int kt = 0; kt < KT; kt++) {
        const int st = kt & 1;
        if (kt + 1 < KT) { cpA(kt + 1, st ^ 1); cpB(W1, kt + 1, st ^ 1); CP_COMMIT(); }
        compute(&sA[st * BM * SA_STRIDE], SA_STRIDE, 0, st);
        if (kt + 1 < KT) CP_WAIT0();
        __syncthreads();
    }

    #pragma unroll
    for (int mi = 0; mi < 4; mi++) {
        int rl = wm * 64 + mi * 16 + (lane >> 2);
        #pragma unroll
        for (int hh = 0; hh < 2; hh++) {
            int rr = rl + hh * 8;
            #pragma unroll
            for (int ni = 0; ni < 4; ni++) {
                int c = wn * 32 + ni * 8 + (lane & 3) * 2;
                float v0 = fmaxf(acc[mi][ni][hh * 2 + 0] + b1[c], 0.f);
                float v1 = fmaxf(acc[mi][ni][hh * 2 + 1] + b1[c + 1], 0.f);
                *(__half2*)&sT[rr * ST_STRIDE + c] = __floats2half2_rn(v0, v1);
                acc[mi][ni][hh * 2 + 0] = 0.f;
                acc[mi][ni][hh * 2 + 1] = 0.f;
            }
        }
    }

    cpB(W2, 0, 0); CP_COMMIT(); CP_WAIT0(); __syncthreads();
    for (int kt = 0; kt < KT; kt++) {
        const int st = kt & 1;
        if (kt + 1 < KT) { cpB(W2, kt + 1, st ^ 1); CP_COMMIT(); }
        compute(sT, ST_STRIDE, kt * BK, st);
        if (kt + 1 < KT) CP_WAIT0();
        __syncthreads();
    }

    #pragma unroll
    for (int mi = 0; mi < 4; mi++) {
        int r0 = mBase + wm * 64 + mi * 16 + (lane >> 2);
        #pragma unroll
        for (int hh = 0; hh < 2; hh++) {
            int r = r0 + hh * 8;
            if (r >= M) continue;
            #pragma unroll
            for (int ni = 0; ni < 4; ni++) {
                int c = wn * 32 + ni * 8 + (lane & 3) * 2;
                float v0 = acc[mi][ni][hh * 2 + 0] + b2[c];
                float v1 = acc[mi][ni][hh * 2 + 1] + b2[c + 1];
                *(__half2*)(h_out + (size_t)r * HIDDEN + c) = __floats2half2_rn(v0, v1);
            }
        }
    }
}

// ---------------------------------------------------------------------------
// Pool (4-way row-parallel) + projection
// ---------------------------------------------------------------------------
__global__ void __launch_bounds__(512) pool_kernel(
    const __half* __restrict__ h,
    const int*    __restrict__ batch,
    float*        __restrict__ pooled)
{
    __shared__ float2 sbuf[4][128];
    int g = blockIdx.x;
    int tid = threadIdx.x;
    int rs = tid >> 7, c2 = tid & 127;

    int lo = 0, hi = N_NODES;
    while (lo < hi) { int mid = (lo + hi) >> 1; if (batch[mid] < g) lo = mid + 1; else hi = mid; }
    int start = lo;
    hi = N_NODES;
    while (lo < hi) { int mid = (lo + hi) >> 1; if (batch[mid] < g + 1) lo = mid + 1; else hi = mid; }
    int end = lo;

    float2 acc = make_float2(0.f, 0.f);
    for (int r = start + rs; r < end; r += 4) {
        float2 f = __half22float2(__ldg((const __half2*)(h + (size_t)r * HIDDEN) + c2));
        acc.x += f.x; acc.y += f.y;
    }
    sbuf[rs][c2] = acc;
    __syncthreads();
    if (rs == 0) {
        float2 s = sbuf[0][c2];
        #pragma unroll
        for (int j = 1; j < 4; j++) { s.x += sbuf[j][c2].x; s.y += sbuf[j][c2].y; }
        float inv = 1.f / fmaxf((float)(end - start), 1.f);
        *(float2*)(pooled + g * HIDDEN + c2 * 2) = make_float2(s.x * inv, s.y * inv);
    }
}

__global__ void __launch_bounds__(HIDDEN) proj_kernel(
    const float* __restrict__ pooled,
    const float* __restrict__ W,
    const float* __restrict__ b,
    float*       __restrict__ out)
{
    int g = blockIdx.x;
    int t = threadIdx.x;
    float acc = b[t];
    #pragma unroll 8
    for (int k = 0; k < HIDDEN; k++)
        acc += pooled[g * HIDDEN + k] * W[k * HIDDEN + t];
    out[g * HIDDEN + t] = acc;
}

// ---------------------------------------------------------------------------
extern "C" void kernel_launch(void* const* d_in, const int* in_sizes, int n_in,
                              void* d_out, int out_size)
{
    const int*   x        = (const int*)  d_in[0];
    const float* x_sem    = (const float*)d_in[1];
    const int*   eattr    = (const int*)  d_in[2];
    const int*   eidx     = (const int*)  d_in[3];
    const int*   batch    = (const int*)  d_in[4];
    const float* label    = (const float*)d_in[5];
    const float* type_emb = (const float*)d_in[6];
    const float* sem_W    = (const float*)d_in[7];
    const float* sem_b    = (const float*)d_in[8];
    const float* role     = (const float*)d_in[9];
    const float* child    = (const float*)d_in[10];
    const float* W1_0     = (const float*)d_in[11];
    const float* b1_0     = (const float*)d_in[12];
    const float* W2_0     = (const float*)d_in[13];
    const float* b2_0     = (const float*)d_in[14];
    const float* W1_1     = (const float*)d_in[15];
    const float* b1_1     = (const float*)d_in[16];
    const float* W2_1     = (const float*)d_in[17];
    const float* b2_1     = (const float*)d_in[18];
    const float* proj_W   = (const float*)d_in[19];
    const float* proj_b   = (const float*)d_in[20];
    float* out = (float*)d_out;

    __half *hP, *zP, *wP, *comboP;
    float *pP;
    int *degP, *offP, *curP, *srcP, *cidP, *bsP;
    cudaGetSymbolAddress((void**)&hP, g_h);
    cudaGetSymbolAddress((void**)&zP, g_z);
    cudaGetSymbolAddress((void**)&wP, g_w16);
    cudaGetSymbolAddress((void**)&comboP, g_combo);
    cudaGetSymbolAddress((void**)&pP, g_pool);
    cudaGetSymbolAddress((void**)&degP, g_deg);
    cudaGetSymbolAddress((void**)&offP, g_off);
    cudaGetSymbolAddress((void**)&curP, g_cur);
    cudaGetSymbolAddress((void**)&srcP, g_csr_src);
    cudaGetSymbolAddress((void**)&cidP, g_csr_cid);
    cudaGetSymbolAddress((void**)&bsP, g_bsum);

    __half* w_sem = wP;
    __half* w1_0  = wP + SEM_IN * HIDDEN;
    __half* w2_0  = w1_0 + HIDDEN * HIDDEN;
    __half* w1_1  = w2_0 + HIDDEN * HIDDEN;
    __half* w2_1  = w1_1 + HIDDEN * HIDDEN;

    const int embed_smem = (SA_ELEMS + SB_ELEMS) * (int)sizeof(__half);
    const int fused_smem = (ST_ELEMS + SA_ELEMS + SB_ELEMS) * (int)sizeof(__half);
    cudaFuncSetAttribute(embed_gemm, cudaFuncAttributeMaxDynamicSharedMemorySize, embed_smem);
    cudaFuncSetAttribute(fused_mlp,  cudaFuncAttributeMaxDynamicSharedMemorySize, fused_smem);

    // setup: weights fp16 + combo table
    cvt_kernel<<<(SEM_IN * HIDDEN / 4 + 255) / 256, 256>>>(sem_W, w_sem, SEM_IN * HIDDEN);
    cvt_kernel<<<(HIDDEN * HIDDEN / 4 + 255) / 256, 256>>>(W1_0, w1_0, HIDDEN * HIDDEN);
    cvt_kernel<<<(HIDDEN * HIDDEN / 4 + 255) / 256, 256>>>(W2_0, w2_0, HIDDEN * HIDDEN);
    cvt_kernel<<<(HIDDEN * HIDDEN / 4 + 255) / 256, 256>>>(W1_1, w1_1, HIDDEN * HIDDEN);
    cvt_kernel<<<(HIDDEN * HIDDEN / 4 + 255) / 256, 256>>>(W2_1, w2_1, HIDDEN * HIDDEN);
    combo_kernel<<<N_COMBO, 128>>>(role, child, comboP);

    // CSR build
    zero_deg_kernel<<<(N_NODES + 255) / 256, 256>>>(degP);
    count_kernel<<<(N_EDGES + 255) / 256, 256>>>(eidx, degP);
    scan1_kernel<<<NBLK, SCAN_B>>>(degP, offP, bsP);
    scan2_kernel<<<1, 128>>>(bsP);
    scan3_kernel<<<(N_NODES + 255) / 256, 256>>>(offP, bsP, curP);
    scatter_kernel<<<(N_EDGES + 255) / 256, 256>>>(eidx, eattr, curP, srcP, cidP);

    const int gemm_blocks = (N_NODES + BM - 1) / BM;   // 782
    const int node_blocks = (N_NODES + 7) / 8;

    // embed
    embed_gemm<<<gemm_blocks, 512, embed_smem>>>(
        x_sem, w_sem, sem_b, x, label, type_emb, hP, N_NODES, SEM_IN);

    // GINE layer 0
    edge_csr_kernel<<<node_blocks, 256>>>(offP, degP, srcP, cidP, comboP, hP, zP);
    fused_mlp<<<gemm_blocks, 512, fused_smem>>>(zP, w1_0, b1_0, w2_0, b2_0, hP, N_NODES);

    // GINE layer 1
    edge_csr_kernel<<<node_blocks, 256>>>(offP, degP, srcP, cidP, comboP, hP, zP);
    fused_mlp<<<gemm_blocks, 512, fused_smem>>>(zP, w1_1, b1_1, w2_1, b2_1, hP, N_NODES);

    // pool + projection
    pool_kernel<<<NUM_GRAPHS, 512>>>(hP, batch, pP);
    proj_kernel<<<NUM_GRAPHS, HIDDEN>>>(pP, proj_W, proj_b, out);
}

// round 6
// speedup vs baseline: 1.3312x; 1.0297x over previous
#include <cuda_runtime.h>
#include <cuda_fp16.h>
#include <stdint.h>

#define N_NODES    100000
#define N_PAD      100096
#define N_EDGES    300000
#define NUM_GRAPHS 128
#define HIDDEN     256
#define SEM_IN     1536
#define MAX_CHILD  200
#define N_COMBO    (8 * MAX_CHILD)
#define SCAN_B     1024
#define NBLK       ((N_NODES + SCAN_B - 1) / SCAN_B)   // 98

// Scratch (zero-initialized device globals)
__device__ __align__(16) __half g_h[(size_t)N_PAD * HIDDEN];
__device__ __align__(16) __half g_z[(size_t)N_PAD * HIDDEN];
__device__ __align__(16) __half g_w16[SEM_IN * HIDDEN + 4 * HIDDEN * HIDDEN];
__device__ __align__(16) __half g_combo[(size_t)N_COMBO * HIDDEN];
__device__ float  g_pool[NUM_GRAPHS * HIDDEN];
__device__ int    g_deg[N_NODES];
__device__ int    g_off[N_NODES];
__device__ int    g_cur[N_NODES];
__device__ int    g_csr_src[N_EDGES];
__device__ int    g_csr_cid[N_EDGES];
__device__ int    g_bsum[SCAN_B];

#define BM 128
#define BK 32
#define SA_STRIDE 40
#define SB_STRIDE 264
#define ST_STRIDE 264
#define SA_ELEMS (2 * BM * SA_STRIDE)
#define SB_ELEMS (2 * BK * SB_STRIDE)
#define ST_ELEMS (BM * ST_STRIDE)

// weight region sizes (elements) in g_w16
#define W_SEM_ELEMS (SEM_IN * HIDDEN)          // 393216
#define W_HH_ELEMS  (HIDDEN * HIDDEN)          // 65536
#define W_TOTAL     (W_SEM_ELEMS + 4 * W_HH_ELEMS)  // 655360

// ---------------------------------------------------------------------------
// helpers
// ---------------------------------------------------------------------------
__device__ __forceinline__ void ldsm_x4(uint32_t* r, const __half* p) {
    uint32_t a = (uint32_t)__cvta_generic_to_shared(p);
    asm volatile("ldmatrix.sync.aligned.m8n8.x4.shared.b16 {%0,%1,%2,%3}, [%4];"
                 : "=r"(r[0]), "=r"(r[1]), "=r"(r[2]), "=r"(r[3]) : "r"(a));
}
__device__ __forceinline__ void ldsm_x4t(uint32_t* r, const __half* p) {
    uint32_t a = (uint32_t)__cvta_generic_to_shared(p);
    asm volatile("ldmatrix.sync.aligned.m8n8.x4.trans.shared.b16 {%0,%1,%2,%3}, [%4];"
                 : "=r"(r[0]), "=r"(r[1]), "=r"(r[2]), "=r"(r[3]) : "r"(a));
}
__device__ __forceinline__ void mma16816(float* c, const uint32_t* a,
                                         uint32_t b0, uint32_t b1) {
    asm volatile(
        "mma.sync.aligned.m16n8k16.row.col.f32.f16.f16.f32 "
        "{%0,%1,%2,%3}, {%4,%5,%6,%7}, {%8,%9}, {%0,%1,%2,%3};"
        : "+f"(c[0]), "+f"(c[1]), "+f"(c[2]), "+f"(c[3])
        : "r"(a[0]), "r"(a[1]), "r"(a[2]), "r"(a[3]), "r"(b0), "r"(b1));
}
__device__ __forceinline__ void cp16(void* smem_dst, const void* gsrc) {
    uint32_t s = (uint32_t)__cvta_generic_to_shared(smem_dst);
    asm volatile("cp.async.cg.shared.global [%0], [%1], 16;" :: "r"(s), "l"(gsrc));
}
#define CP_COMMIT() asm volatile("cp.async.commit_group;")
#define CP_WAIT0()  asm volatile("cp.async.wait_group 0;")

// ---------------------------------------------------------------------------
// setup: ONE kernel converts all 5 weight matrices to fp16 AND zeroes deg.
// Element space: [0, W_TOTAL) -> weights; [W_TOTAL, W_TOTAL + N_NODES) -> deg=0
// ---------------------------------------------------------------------------
#define CVT_TOTAL   (W_TOTAL + N_NODES + 24)   // pad so /4 covers deg fully
__global__ void cvt_all_kernel(const float* __restrict__ sem_W,
                               const float* __restrict__ W1_0, const float* __restrict__ W2_0,
                               const float* __restrict__ W1_1, const float* __restrict__ W2_1,
                               __half* __restrict__ dst, int* __restrict__ deg)
{
    int e = (blockIdx.x * blockDim.x + threadIdx.x) * 4;
    if (e < W_TOTAL) {
        const float* src;
        int local = e;
        if (local < W_SEM_ELEMS) { src = sem_W; }
        else {
            local -= W_SEM_ELEMS;
            int w = local / W_HH_ELEMS;
            local -= w * W_HH_ELEMS;
            src = (w == 0) ? W1_0 : (w == 1) ? W2_0 : (w == 2) ? W1_1 : W2_1;
        }
        float4 v = *(const float4*)(src + local);
        __half2* d = (__half2*)(dst + e);
        d[0] = __floats2half2_rn(v.x, v.y);
        d[1] = __floats2half2_rn(v.z, v.w);
    } else {
        int i = e - W_TOTAL;
        #pragma unroll
        for (int j = 0; j < 4; j++)
            if (i + j < N_NODES) deg[i + j] = 0;
    }
}

__global__ void combo_kernel(const float* __restrict__ role, const float* __restrict__ child,
                             __half* __restrict__ combo) {
    int rc = blockIdx.x;
    int r = rc / MAX_CHILD, cc = rc % MAX_CHILD;
    int t = threadIdx.x;                      // 128
    float2 a = *(const float2*)(role + r * HIDDEN + t * 2);
    float2 b = *(const float2*)(child + cc * HIDDEN + t * 2);
    *(__half2*)(combo + (size_t)rc * HIDDEN + t * 2) = __floats2half2_rn(a.x + b.x, a.y + b.y);
}

// ---------------------------------------------------------------------------
// CSR build
// ---------------------------------------------------------------------------
__global__ void count_kernel(const int* __restrict__ eidx, int* __restrict__ deg) {
    int e = blockIdx.x * blockDim.x + threadIdx.x;
    if (e < N_EDGES) atomicAdd(&deg[eidx[N_EDGES + e]], 1);
}
__global__ void __launch_bounds__(SCAN_B) scan1_kernel(
    const int* __restrict__ deg, int* __restrict__ off, int* __restrict__ bsum)
{
    __shared__ int s[SCAN_B];
    int tid = threadIdx.x;
    int i = blockIdx.x * SCAN_B + tid;
    int v = (i < N_NODES) ? deg[i] : 0;
    s[tid] = v; __syncthreads();
    #pragma unroll
    for (int d = 1; d < SCAN_B; d <<= 1) {
        int t = (tid >= d) ? s[tid - d] : 0;
        __syncthreads();
        if (tid >= d) s[tid] += t;
        __syncthreads();
    }
    if (i < N_NODES) off[i] = s[tid] - v;
    if (tid == SCAN_B - 1) bsum[blockIdx.x] = s[tid];
}
__global__ void __launch_bounds__(128) scan2_kernel(int* bsum) {
    __shared__ int s[128];
    int tid = threadIdx.x;
    int v = (tid < NBLK) ? bsum[tid] : 0;
    s[tid] = v; __syncthreads();
    #pragma unroll
    for (int d = 1; d < 128; d <<= 1) {
        int t = (tid >= d) ? s[tid - d] : 0;
        __syncthreads();
        if (tid >= d) s[tid] += t;
        __syncthreads();
    }
    if (tid < NBLK) bsum[tid] = s[tid] - v;
}
__global__ void scan3_kernel(int* __restrict__ off, const int* __restrict__ bsum,
                             int* __restrict__ cur) {
    int i = blockIdx.x * blockDim.x + threadIdx.x;
    if (i < N_NODES) {
        int o = off[i] + bsum[i >> 10];
        off[i] = o;
        cur[i] = o;
    }
}
__global__ void scatter_kernel(const int* __restrict__ eidx, const int* __restrict__ eattr,
                               int* __restrict__ cur,
                               int* __restrict__ csr_src, int* __restrict__ csr_cid) {
    int e = blockIdx.x * blockDim.x + threadIdx.x;
    if (e < N_EDGES) {
        int pos = atomicAdd(&cur[eidx[N_EDGES + e]], 1);
        csr_src[pos] = eidx[e];
        int r  = eattr[2 * e];
        int cc = min(max(eattr[2 * e + 1], 0), MAX_CHILD - 1);
        csr_cid[pos] = r * MAX_CHILD + cc;
    }
}

// ---------------------------------------------------------------------------
// Edge aggregation (CSR, atomic-free, unroll-2 index prefetch).
// z[n] = h[n] + sum_e relu(h[src_e] + combo[cid_e])
// ---------------------------------------------------------------------------
__global__ void __launch_bounds__(256) edge_csr_kernel(
    const int*    __restrict__ off,
    const int*    __restrict__ deg,
    const int*    __restrict__ csr_src,
    const int*    __restrict__ csr_cid,
    const __half* __restrict__ combo,
    const __half* __restrict__ h,
    __half*       __restrict__ z)
{
    int n = blockIdx.x * 8 + (threadIdx.x >> 5);
    if (n >= N_NODES) return;
    int lane = threadIdx.x & 31;

    float4 hv = __ldg((const float4*)(h + (size_t)n * HIDDEN) + lane);
    __half2* hp = (__half2*)&hv;
    float2 a0 = __half22float2(hp[0]), a1 = __half22float2(hp[1]);
    float2 a2 = __half22float2(hp[2]), a3 = __half22float2(hp[3]);
    float acc[8] = {a0.x, a0.y, a1.x, a1.y, a2.x, a2.y, a3.x, a3.y};

    int start = off[n];
    int d = deg[n];
    int k = 0;

    // unroll-2: both iterations' indices loaded first -> 4 independent gathers
    for (; k + 2 <= d; k += 2) {
        int s0 = __ldg(&csr_src[start + k]);
        int c0 = __ldg(&csr_cid[start + k]);
        int s1 = __ldg(&csr_src[start + k + 1]);
        int c1 = __ldg(&csr_cid[start + k + 1]);

        float4 sv0 = __ldg((const float4*)(h + (size_t)s0 * HIDDEN) + lane);
        float4 cv0 = __ldg((const float4*)(combo + (size_t)c0 * HIDDEN) + lane);
        float4 sv1 = __ldg((const float4*)(h + (size_t)s1 * HIDDEN) + lane);
        float4 cv1 = __ldg((const float4*)(combo + (size_t)c1 * HIDDEN) + lane);

        __half2* sp0 = (__half2*)&sv0; __half2* cp0 = (__half2*)&cv0;
        __half2* sp1 = (__half2*)&sv1; __half2* cp1 = (__half2*)&cv1;
        #pragma unroll
        for (int j = 0; j < 4; j++) {
            float2 f0 = __half22float2(sp0[j]);
            float2 g0 = __half22float2(cp0[j]);
            float2 f1 = __half22float2(sp1[j]);
            float2 g1 = __half22float2(cp1[j]);
            acc[2 * j + 0] += fmaxf(f0.x + g0.x, 0.f) + fmaxf(f1.x + g1.x, 0.f);
            acc[2 * j + 1] += fmaxf(f0.y + g0.y, 0.f) + fmaxf(f1.y + g1.y, 0.f);
        }
    }
    if (k < d) {
        int s0 = __ldg(&csr_src[start + k]);
        int c0 = __ldg(&csr_cid[start + k]);
        float4 sv0 = __ldg((const float4*)(h + (size_t)s0 * HIDDEN) + lane);
        float4 cv0 = __ldg((const float4*)(combo + (size_t)c0 * HIDDEN) + lane);
        __half2* sp0 = (__half2*)&sv0; __half2* cp0 = (__half2*)&cv0;
        #pragma unroll
        for (int j = 0; j < 4; j++) {
            float2 f0 = __half22float2(sp0[j]);
            float2 g0 = __half22float2(cp0[j]);
            acc[2 * j + 0] += fmaxf(f0.x + g0.x, 0.f);
            acc[2 * j + 1] += fmaxf(f0.y + g0.y, 0.f);
        }
    }

    float4 outv;
    __half2* op = (__half2*)&outv;
    op[0] = __floats2half2_rn(acc[0], acc[1]);
    op[1] = __floats2half2_rn(acc[2], acc[3]);
    op[2] = __floats2half2_rn(acc[4], acc[5]);
    op[3] = __floats2half2_rn(acc[6], acc[7]);
    ((float4*)(z + (size_t)n * HIDDEN))[lane] = outv;
}

// ---------------------------------------------------------------------------
// Embed GEMM (mma.sync): h16 = x_sem(fp32)@sem_W16 + sem_b + label[x0] + type[x1]
// BM=128, BN=256, BK=32, 512 threads; A reg-staged fp32->fp16; B cp.async fp16.
// ---------------------------------------------------------------------------
__global__ void __launch_bounds__(512) embed_gemm(
    const float* __restrict__ A, const __half* __restrict__ B,
    const float* __restrict__ bias,
    const int*   __restrict__ xidx,
    const float* __restrict__ label_emb,
    const float* __restrict__ type_emb,
    __half* __restrict__ h_out, int M, int K)
{
    extern __shared__ __half smem[];
    __half* sA = smem;
    __half* sB = smem + SA_ELEMS;

    const int tid  = threadIdx.x;
    const int lane = tid & 31;
    const int warp = tid >> 5;
    const int wm   = warp >> 3;
    const int wn   = warp & 7;
    const int mBase = blockIdx.x * BM;

    const int a_row = tid >> 3;
    const int a_col = (tid & 7) << 2;
    const int b_row = tid >> 4;
    const int b_col = (tid & 15) << 3;

    const int KT = K / BK;

    float4 ra[2];
    float acc[4][4][4];
    #pragma unroll
    for (int i = 0; i < 4; i++)
        #pragma unroll
        for (int j = 0; j < 4; j++)
            #pragma unroll
            for (int q = 0; q < 4; q++) acc[i][j][q] = 0.f;

    auto ldgA = [&](int kt) {
        #pragma unroll
        for (int i = 0; i < 2; i++) {
            int r = mBase + a_row + i * 64;
            if (r < M) ra[i] = *(const float4*)(A + (size_t)r * K + kt * BK + a_col);
            else       ra[i] = make_float4(0.f, 0.f, 0.f, 0.f);
        }
    };
    auto stsA = [&](int st) {
        #pragma unroll
        for (int i = 0; i < 2; i++) {
            __half2* p = (__half2*)&sA[st * BM * SA_STRIDE + (a_row + i * 64) * SA_STRIDE + a_col];
            p[0] = __floats2half2_rn(ra[i].x, ra[i].y);
            p[1] = __floats2half2_rn(ra[i].z, ra[i].w);
        }
    };
    auto cpB = [&](int kt, int st) {
        const __half* g = B + (size_t)(kt * BK + b_row) * HIDDEN + b_col;
        __half* s = &sB[st * BK * SB_STRIDE + b_row * SB_STRIDE + b_col];
        cp16(s, g);
        cp16(s + 128, g + 128);
    };

    ldgA(0); cpB(0, 0); CP_COMMIT();
    stsA(0); CP_WAIT0(); __syncthreads();

    for (int kt = 0; kt < KT; kt++) {
        const int st = kt & 1;
        if (kt + 1 < KT) { ldgA(kt + 1); cpB(kt + 1, st ^ 1); CP_COMMIT(); }
        #pragma unroll
        for (int ks = 0; ks < 2; ks++) {
            uint32_t af[4][4], bf[2][4];
            #pragma unroll
            for (int mi = 0; mi < 4; mi++)
                ldsm_x4(af[mi], &sA[st * BM * SA_STRIDE
                         + (wm * 64 + mi * 16 + (lane & 15)) * SA_STRIDE
                         + ks * 16 + (lane >> 4) * 8]);
            #pragma unroll
            for (int p2 = 0; p2 < 2; p2++) {
                int krow = ks * 16 + (lane & 7) + ((lane >> 3) & 1) * 8;
                int ncol = wn * 32 + p2 * 16 + (lane >> 4) * 8;
                ldsm_x4t(bf[p2], &sB[st * BK * SB_STRIDE + krow * SB_STRIDE + ncol]);
            }
            #pragma unroll
            for (int mi = 0; mi < 4; mi++)
                #pragma unroll
                for (int ni = 0; ni < 4; ni++)
                    mma16816(acc[mi][ni], af[mi],
                             bf[ni >> 1][(ni & 1) * 2 + 0], bf[ni >> 1][(ni & 1) * 2 + 1]);
        }
        if (kt + 1 < KT) { stsA(st ^ 1); CP_WAIT0(); }
        __syncthreads();
    }

    #pragma unroll
    for (int mi = 0; mi < 4; mi++) {
        int r0 = mBase + wm * 64 + mi * 16 + (lane >> 2);
        #pragma unroll
        for (int hh = 0; hh < 2; hh++) {
            int r = r0 + hh * 8;
            if (r >= M) continue;
            int x0 = xidx[2 * r], x1 = xidx[2 * r + 1];
            #pragma unroll
            for (int ni = 0; ni < 4; ni++) {
                int c = wn * 32 + ni * 8 + (lane & 3) * 2;
                float v0 = acc[mi][ni][hh * 2 + 0] + bias[c]
                         + label_emb[(size_t)x0 * HIDDEN + c] + type_emb[x1 * HIDDEN + c];
                float v1 = acc[mi][ni][hh * 2 + 1] + bias[c + 1]
                         + label_emb[(size_t)x0 * HIDDEN + c + 1] + type_emb[x1 * HIDDEN + c + 1];
                *(__half2*)(h_out + (size_t)r * HIDDEN + c) = __floats2half2_rn(v0, v1);
            }
        }
    }
}

// ---------------------------------------------------------------------------
// Fused MLP: h16 = relu(z16 @ W1_16 + b1) @ W2_16 + b2 (t staged in smem)
// ---------------------------------------------------------------------------
__global__ void __launch_bounds__(512) fused_mlp(
    const __half* __restrict__ Z,
    const __half* __restrict__ W1, const float* __restrict__ b1,
    const __half* __restrict__ W2, const float* __restrict__ b2,
    __half* __restrict__ h_out, int M)
{
    extern __shared__ __half hsm[];
    __half* sT = hsm;
    __half* sA = hsm + ST_ELEMS;
    __half* sB = hsm + ST_ELEMS + SA_ELEMS;

    const int tid  = threadIdx.x;
    const int lane = tid & 31;
    const int warp = tid >> 5;
    const int wm   = warp >> 3;
    const int wn   = warp & 7;
    const int mBase = blockIdx.x * BM;

    const int a_row = tid >> 2;
    const int a_col = (tid & 3) << 3;
    const int b_row = tid >> 4;
    const int b_col = (tid & 15) << 3;

    const int KT = HIDDEN / BK;

    float acc[4][4][4];
    #pragma unroll
    for (int i = 0; i < 4; i++)
        #pragma unroll
        for (int j = 0; j < 4; j++)
            #pragma unroll
            for (int q = 0; q < 4; q++) acc[i][j][q] = 0.f;

    auto cpA = [&](int kt, int st) {
        cp16(&sA[st * BM * SA_STRIDE + a_row * SA_STRIDE + a_col],
             Z + (size_t)(mBase + a_row) * HIDDEN + kt * BK + a_col);
    };
    auto cpB = [&](const __half* W, int kt, int st) {
        const __half* g = W + (size_t)(kt * BK + b_row) * HIDDEN + b_col;
        __half* s = &sB[st * BK * SB_STRIDE + b_row * SB_STRIDE + b_col];
        cp16(s, g);
        cp16(s + 128, g + 128);
    };
    auto compute = [&](const __half* aBase, int aStride, int aColOff, int st) {
        #pragma unroll
        for (int ks = 0; ks < 2; ks++) {
            uint32_t af[4][4], bf[2][4];
            #pragma unroll
            for (int mi = 0; mi < 4; mi++)
                ldsm_x4(af[mi], aBase
                         + (wm * 64 + mi * 16 + (lane & 15)) * aStride
                         + aColOff + ks * 16 + (lane >> 4) * 8);
            #pragma unroll
            for (int p2 = 0; p2 < 2; p2++) {
                int krow = ks * 16 + (lane & 7) + ((lane >> 3) & 1) * 8;
                int ncol = wn * 32 + p2 * 16 + (lane >> 4) * 8;
                ldsm_x4t(bf[p2], &sB[st * BK * SB_STRIDE + krow * SB_STRIDE + ncol]);
            }
            #pragma unroll
            for (int mi = 0; mi < 4; mi++)
                #pragma unroll
                for (int ni = 0; ni < 4; ni++)
                    mma16816(acc[mi][ni], af[mi],
                             bf[ni >> 1][(ni & 1) * 2 + 0], bf[ni >> 1][(ni & 1) * 2 + 1]);
        }
    };

    cpA(0, 0); cpB(W1, 0, 0); CP_COMMIT(); CP_WAIT0(); __syncthreads();
    for (int kt = 0; kt < KT; kt++) {
        const int st = kt & 1;
        if (kt + 1 < KT) { cpA(kt + 1, st ^ 1); cpB(W1, kt + 1, st ^ 1); CP_COMMIT(); }
        compute(&sA[st * BM * SA_STRIDE], SA_STRIDE, 0, st);
        if (kt + 1 < KT) CP_WAIT0();
        __syncthreads();
    }

    #pragma unroll
    for (int mi = 0; mi < 4; mi++) {
        int rl = wm * 64 + mi * 16 + (lane >> 2);
        #pragma unroll
        for (int hh = 0; hh < 2; hh++) {
            int rr = rl + hh * 8;
            #pragma unroll
            for (int ni = 0; ni < 4; ni++) {
                int c = wn * 32 + ni * 8 + (lane & 3) * 2;
                float v0 = fmaxf(acc[mi][ni][hh * 2 + 0] + b1[c], 0.f);
                float v1 = fmaxf(acc[mi][ni][hh * 2 + 1] + b1[c + 1], 0.f);
                *(__half2*)&sT[rr * ST_STRIDE + c] = __floats2half2_rn(v0, v1);
                acc[mi][ni][hh * 2 + 0] = 0.f;
                acc[mi][ni][hh * 2 + 1] = 0.f;
            }
        }
    }

    cpB(W2, 0, 0); CP_COMMIT(); CP_WAIT0(); __syncthreads();
    for (int kt = 0; kt < KT; kt++) {
        const int st = kt & 1;
        if (kt + 1 < KT) { cpB(W2, kt + 1, st ^ 1); CP_COMMIT(); }
        compute(sT, ST_STRIDE, kt * BK, st);
        if (kt + 1 < KT) CP_WAIT0();
        __syncthreads();
    }

    #pragma unroll
    for (int mi = 0; mi < 4; mi++) {
        int r0 = mBase + wm * 64 + mi * 16 + (lane >> 2);
        #pragma unroll
        for (int hh = 0; hh < 2; hh++) {
            int r = r0 + hh * 8;
            if (r >= M) continue;
            #pragma unroll
            for (int ni = 0; ni < 4; ni++) {
                int c = wn * 32 + ni * 8 + (lane & 3) * 2;
                float v0 = acc[mi][ni][hh * 2 + 0] + b2[c];
                float v1 = acc[mi][ni][hh * 2 + 1] + b2[c + 1];
                *(__half2*)(h_out + (size_t)r * HIDDEN + c) = __floats2half2_rn(v0, v1);
            }
        }
    }
}

// ---------------------------------------------------------------------------
// Pool (4-way row-parallel) + projection
// ---------------------------------------------------------------------------
__global__ void __launch_bounds__(512) pool_kernel(
    const __half* __restrict__ h,
    const int*    __restrict__ batch,
    float*        __restrict__ pooled)
{
    __shared__ float2 sbuf[4][128];
    int g = blockIdx.x;
    int tid = threadIdx.x;
    int rs = tid >> 7, c2 = tid & 127;

    int lo = 0, hi = N_NODES;
    while (lo < hi) { int mid = (lo + hi) >> 1; if (batch[mid] < g) lo = mid + 1; else hi = mid; }
    int start = lo;
    hi = N_NODES;
    while (lo < hi) { int mid = (lo + hi) >> 1; if (batch[mid] < g + 1) lo = mid + 1; else hi = mid; }
    int end = lo;

    float2 acc = make_float2(0.f, 0.f);
    for (int r = start + rs; r < end; r += 4) {
        float2 f = __half22float2(__ldg((const __half2*)(h + (size_t)r * HIDDEN) + c2));
        acc.x += f.x; acc.y += f.y;
    }
    sbuf[rs][c2] = acc;
    __syncthreads();
    if (rs == 0) {
        float2 s = sbuf[0][c2];
        #pragma unroll
        for (int j = 1; j < 4; j++) { s.x += sbuf[j][c2].x; s.y += sbuf[j][c2].y; }
        float inv = 1.f / fmaxf((float)(end - start), 1.f);
        *(float2*)(pooled + g * HIDDEN + c2 * 2) = make_float2(s.x * inv, s.y * inv);
    }
}

__global__ void __launch_bounds__(HIDDEN) proj_kernel(
    const float* __restrict__ pooled,
    const float* __restrict__ W,
    const float* __restrict__ b,
    float*       __restrict__ out)
{
    int g = blockIdx.x;
    int t = threadIdx.x;
    float acc = b[t];
    #pragma unroll 8
    for (int k = 0; k < HIDDEN; k++)
        acc += pooled[g * HIDDEN + k] * W[k * HIDDEN + t];
    out[g * HIDDEN + t] = acc;
}

// ---------------------------------------------------------------------------
extern "C" void kernel_launch(void* const* d_in, const int* in_sizes, int n_in,
                              void* d_out, int out_size)
{
    const int*   x        = (const int*)  d_in[0];
    const float* x_sem    = (const float*)d_in[1];
    const int*   eattr    = (const int*)  d_in[2];
    const int*   eidx     = (const int*)  d_in[3];
    const int*   batch    = (const int*)  d_in[4];
    const float* label    = (const float*)d_in[5];
    const float* type_emb = (const float*)d_in[6];
    const float* sem_W    = (const float*)d_in[7];
    const float* sem_b    = (const float*)d_in[8];
    const float* role     = (const float*)d_in[9];
    const float* child    = (const float*)d_in[10];
    const float* W1_0     = (const float*)d_in[11];
    const float* b1_0     = (const float*)d_in[12];
    const float* W2_0     = (const float*)d_in[13];
    const float* b2_0     = (const float*)d_in[14];
    const float* W1_1     = (const float*)d_in[15];
    const float* b1_1     = (const float*)d_in[16];
    const float* W2_1     = (const float*)d_in[17];
    const float* b2_1     = (const float*)d_in[18];
    const float* proj_W   = (const float*)d_in[19];
    const float* proj_b   = (const float*)d_in[20];
    float* out = (float*)d_out;

    __half *hP, *zP, *wP, *comboP;
    float *pP;
    int *degP, *offP, *curP, *srcP, *cidP, *bsP;
    cudaGetSymbolAddress((void**)&hP, g_h);
    cudaGetSymbolAddress((void**)&zP, g_z);
    cudaGetSymbolAddress((void**)&wP, g_w16);
    cudaGetSymbolAddress((void**)&comboP, g_combo);
    cudaGetSymbolAddress((void**)&pP, g_pool);
    cudaGetSymbolAddress((void**)&degP, g_deg);
    cudaGetSymbolAddress((void**)&offP, g_off);
    cudaGetSymbolAddress((void**)&curP, g_cur);
    cudaGetSymbolAddress((void**)&srcP, g_csr_src);
    cudaGetSymbolAddress((void**)&cidP, g_csr_cid);
    cudaGetSymbolAddress((void**)&bsP, g_bsum);

    __half* w_sem = wP;
    __half* w1_0  = wP + W_SEM_ELEMS;
    __half* w2_0  = w1_0 + W_HH_ELEMS;
    __half* w1_1  = w2_0 + W_HH_ELEMS;
    __half* w2_1  = w1_1 + W_HH_ELEMS;

    const int embed_smem = (SA_ELEMS + SB_ELEMS) * (int)sizeof(__half);
    const int fused_smem = (ST_ELEMS + SA_ELEMS + SB_ELEMS) * (int)sizeof(__half);
    cudaFuncSetAttribute(embed_gemm, cudaFuncAttributeMaxDynamicSharedMemorySize, embed_smem);
    cudaFuncSetAttribute(fused_mlp,  cudaFuncAttributeMaxDynamicSharedMemorySize, fused_smem);

    const int gemm_blocks = (N_NODES + BM - 1) / BM;   // 782
    const int node_blocks = (N_NODES + 7) / 8;

    // Launch order places embed_gemm 6th so ncu (-s 5 -c 1) profiles it.
    // (1) all weight conversions + deg zeroing in one kernel
    cvt_all_kernel<<<(CVT_TOTAL / 4 + 255) / 256, 256>>>(
        sem_W, W1_0, W2_0, W1_1, W2_1, wP, degP);
    // (2) combo table
    combo_kernel<<<N_COMBO, 128>>>(role, child, comboP);
    // (3,4,5) CSR part 1 (independent of embed)
    count_kernel<<<(N_EDGES + 255) / 256, 256>>>(eidx, degP);
    scan1_kernel<<<NBLK, SCAN_B>>>(degP, offP, bsP);
    scan2_kernel<<<1, 128>>>(bsP);
    // (6) embed — PROFILED LAUNCH
    embed_gemm<<<gemm_blocks, 512, embed_smem>>>(
        x_sem, w_sem, sem_b, x, label, type_emb, hP, N_NODES, SEM_IN);
    // CSR part 2
    scan3_kernel<<<(N_NODES + 255) / 256, 256>>>(offP, bsP, curP);
    scatter_kernel<<<(N_EDGES + 255) / 256, 256>>>(eidx, eattr, curP, srcP, cidP);

    // GINE layer 0
    edge_csr_kernel<<<node_blocks, 256>>>(offP, degP, srcP, cidP, comboP, hP, zP);
    fused_mlp<<<gemm_blocks, 512, fused_smem>>>(zP, w1_0, b1_0, w2_0, b2_0, hP, N_NODES);

    // GINE layer 1
    edge_csr_kernel<<<node_blocks, 256>>>(offP, degP, srcP, cidP, comboP, hP, zP);
    fused_mlp<<<gemm_blocks, 512, fused_smem>>>(zP, w1_1, b1_1, w2_1, b2_1, hP, N_NODES);

    // pool + projection
    pool_kernel<<<NUM_GRAPHS, 512>>>(hP, batch, pP);
    proj_kernel<<<NUM_GRAPHS, HIDDEN>>>(pP, proj_W, proj_b, out);
}